// round 5
// baseline (speedup 1.0000x reference)
#include <cuda_runtime.h>

#define SEQ   2048          // B * CK
#define CKD   128
#define NSEQ  8192
#define W3    (128*128*128)

// ---------------- static device scratch (no allocations allowed) ----------------
__device__ float  g_xt[SEQ * NSEQ];      // transposed input x0 (B,CK,N); later recon buf A
__device__ float2 g_z  [SEQ * 4096];     // packed d + i*s per level; later recon buf B
__device__ float  g_x0 [SEQ * 4096];     // smooth coeffs, odd levels (x1, x3, ...)
__device__ float  g_x1 [SEQ * 2048];     // smooth coeffs, even levels (x2, x4, ...)
__device__ float2 g_Df [128 * SEQ];      // (mode, b, i) spectra of d
__device__ float2 g_Sf [128 * SEQ];      // (mode, b, i) spectra of s
__device__ float2 g_pud[512 * SEQ];      // partial UdF per i-chunk
__device__ float2 g_pus[512 * SEQ];      // partial UsF per i-chunk
__device__ float  g_wt [6 * W3];         // weights transposed to (w, mode, i, o)
__device__ float  g_Ud [SEQ * 8191];     // stored detail outputs, all levels
__device__ float  g_Us [SEQ * 8191];     // stored smooth outputs, all levels
__device__ float2 g_tw [2048];           // tw[x] = exp(-2*pi*i*x/4096), x < 2048

// ---------------- twiddle table (built once per call, precise sincosf) ----------------
__global__ void k_tw() {
    int x = blockIdx.x * blockDim.x + threadIdx.x;
    if (x >= 2048) return;
    float ang = -6.283185307179586f * (float)x / 4096.0f;
    float s, c;
    sincosf(ang, &s, &c);
    g_tw[x] = make_float2(c, s);
}

// ---------------- input transpose: (B,N,C,K) -> (B, CK, N) ----------------
__global__ void k_tin(const float* __restrict__ x) {
    __shared__ float tile[32][129];
    int b  = blockIdx.x >> 8;            // 256 n-tiles per batch
    int n0 = (blockIdx.x & 255) << 5;
    const float* src = x + ((size_t)b * NSEQ + n0) * CKD;
    for (int idx = threadIdx.x; idx < 32 * 128; idx += blockDim.x) {
        int r = idx >> 7, cc = idx & 127;
        tile[r][cc] = src[(size_t)r * CKD + cc];
    }
    __syncthreads();
    float* dst = g_xt + (size_t)b * CKD * NSEQ + n0;
    for (int idx = threadIdx.x; idx < 32 * 128; idx += blockDim.x) {
        int ck = idx >> 5, j = idx & 31;
        dst[(size_t)ck * NSEQ + j] = tile[j][ck];
    }
}

// ---------------- weight transpose: (i,o,mode) -> (mode,i,o), per weight w ----------------
__global__ void k_wt(const float* __restrict__ wAr, const float* __restrict__ wAi,
                     const float* __restrict__ wBr, const float* __restrict__ wBi,
                     const float* __restrict__ wCr, const float* __restrict__ wCi) {
    __shared__ float tile[32][33];
    int w = blockIdx.z;
    int i = blockIdx.y;
    int ot = (blockIdx.x >> 2) << 5;     // o-tile base
    int mt = (blockIdx.x & 3) << 5;      // mode-tile base
    const float* src;
    switch (w) {
        case 0: src = wAr; break; case 1: src = wAi; break;
        case 2: src = wBr; break; case 3: src = wBi; break;
        case 4: src = wCr; break; default: src = wCi; break;
    }
    int tx = threadIdx.x, ty = threadIdx.y;     // (32, 8)
    #pragma unroll
    for (int j = 0; j < 32; j += 8)
        tile[ty + j][tx] = src[((size_t)i * 128 + ot + ty + j) * 128 + mt + tx];
    __syncthreads();
    float* dst = g_wt + (size_t)w * W3;
    #pragma unroll
    for (int j = 0; j < 32; j += 8)
        dst[((size_t)(mt + ty + j) * 128 + i) * 128 + ot + tx] = tile[tx][ty + j];
}

// ---------------- decompose: filter bank + pack z = d + i*s ----------------
__global__ void k_dec(const float* __restrict__ xin, int m,
                      float* __restrict__ xnext,
                      const float* __restrict__ ecs, const float* __restrict__ ecd) {
    int id = blockIdx.x * blockDim.x + threadIdx.x;
    if (id >= 512 * m) return;
    int t = id % m;
    int bc = id / m;                 // b*32 + c
    int row0 = bc * 4;               // == b*128 + c*4
    int n = 2 * m;
    float xa[8];
    #pragma unroll
    for (int k = 0; k < 4; k++) {
        const float* p = xin + (size_t)(row0 + k) * n + 2 * t;
        xa[k]     = p[0];            // even sample
        xa[4 + k] = p[1];            // odd sample
    }
    #pragma unroll
    for (int kp = 0; kp < 4; kp++) {
        float d = 0.f, s = 0.f;
        #pragma unroll
        for (int j = 0; j < 8; j++) {
            d += xa[j] * __ldg(&ecd[j * 4 + kp]);
            s += xa[j] * __ldg(&ecs[j * 4 + kp]);
        }
        size_t o = (size_t)(row0 + kp) * m + t;
        g_z[o] = make_float2(d, s);
        xnext[o] = s;
    }
}

// ---------------- in-place radix-2 FFT on shared memory, table twiddles ----------------
// tw[x] = exp(-2*pi*i*x/4096); stage st uses tw[j * (4096>>st)], j < 2^(st-1).
template <int INV>
__device__ __forceinline__ void fft_sm(float2* sb, int m, int logm) {
    int T = blockDim.x;
    for (int st = 1; st <= logm; st++) {
        int half = 1 << (st - 1);
        int tws  = 4096 >> st;
        for (int idx = threadIdx.x; idx < (m >> 1); idx += T) {
            int j = idx & (half - 1);
            int pos = ((idx >> (st - 1)) << st) + j;
            float2 w = __ldg(&g_tw[j * tws]);
            float cw = w.x;
            float sw = INV ? -w.y : w.y;
            float2 u = sb[pos], v = sb[pos + half];
            float2 tv = make_float2(v.x * cw - v.y * sw, v.x * sw + v.y * cw);
            sb[pos]        = make_float2(u.x + tv.x, u.y + tv.y);
            sb[pos + half] = make_float2(u.x - tv.x, u.y - tv.y);
        }
        __syncthreads();
    }
}

// ---------------- forward FFT of packed z, split into Df / Sf ----------------
__global__ void k_fftf(int m, int logm, int l) {
    extern __shared__ float2 sb[];
    int s = blockIdx.x;
    int T = blockDim.x;
    const float2* zin = g_z + (size_t)s * m;
    for (int t = threadIdx.x; t < m; t += T) {
        int r = logm ? (int)(__brev((unsigned)t) >> (32 - logm)) : 0;
        sb[r] = zin[t];
    }
    __syncthreads();
    fft_sm<0>(sb, m, logm);
    for (int k = threadIdx.x; k < l; k += T) {
        float2 Zk = sb[k];
        float2 Zm = sb[(m - k) & (m - 1)];
        // Df = (Z[k] + conj(Z[m-k]))/2 ; Sf = -i*(Z[k] - conj(Z[m-k]))/2
        float2 Df = make_float2(0.5f * (Zk.x + Zm.x), 0.5f * (Zk.y - Zm.y));
        float2 Sf = make_float2(0.5f * (Zk.y + Zm.y), 0.5f * (Zm.x - Zk.x));
        g_Df[(size_t)k * SEQ + s] = Df;
        g_Sf[(size_t)k * SEQ + s] = Sf;
    }
}

// ---------------- per-mode complex channel mixing (partial over i-chunk) ----------------
__global__ void __launch_bounds__(128) k_mix(int l, int ilen) {
    __shared__ float2 sdf[16][32], ssf[16][32];
    int mode = blockIdx.x, ch = blockIdx.y;
    int i0 = ch * ilen;
    int cnt = 16 * ilen;
    for (int idx = threadIdx.x; idx < cnt; idx += 128) {
        int bb = idx / ilen, ii = idx - bb * ilen;
        size_t src = (size_t)mode * SEQ + bb * 128 + i0 + ii;
        sdf[bb][ii] = g_Df[src];
        ssf[bb][ii] = g_Sf[src];
    }
    __syncthreads();
    int o = threadIdx.x;
    float udr[16], udi[16], usr[16], usi[16];
    #pragma unroll
    for (int b = 0; b < 16; b++) { udr[b] = udi[b] = usr[b] = usi[b] = 0.f; }
    for (int ii = 0; ii < ilen; ii++) {
        size_t widx = ((size_t)mode * 128 + (i0 + ii)) * 128 + o;
        float ar = g_wt[widx],          ai = g_wt[W3 + widx];
        float br = g_wt[2 * W3 + widx], bi = g_wt[3 * W3 + widx];
        float cr = g_wt[4 * W3 + widx], ci = g_wt[5 * W3 + widx];
        #pragma unroll
        for (int b = 0; b < 16; b++) {
            float2 df = sdf[b][ii], sf = ssf[b][ii];
            udr[b] += df.x * ar - df.y * ai + sf.x * br - sf.y * bi;
            udi[b] += df.x * ai + df.y * ar + sf.x * bi + sf.y * br;
            usr[b] += df.x * cr - df.y * ci;
            usi[b] += df.x * ci + df.y * cr;
        }
    }
    size_t base = ((size_t)ch * l + mode) * SEQ + o;
    #pragma unroll
    for (int b = 0; b < 16; b++) {
        g_pud[base + b * 128] = make_float2(udr[b], udi[b]);
        g_pus[base + b * 128] = make_float2(usr[b], usi[b]);
    }
}

// ---------------- inverse FFT: sum partials, assemble Hermitian spectrum, store Ud/Us ----------------
__global__ void k_ffti(int m, int logm, int l, int nch, size_t off) {
    extern __shared__ float2 sb[];
    int s = blockIdx.x;
    int T = blockDim.x;
    for (int k = threadIdx.x; k < m; k += T) {
        float2 Z = make_float2(0.f, 0.f);
        int j = -1, cj = 0;
        if (k < l) { j = k; }
        else { int jm = m - k; if (jm < l) { j = jm; cj = 1; } }
        if (j >= 0) {
            float udx = 0.f, udy = 0.f, usx = 0.f, usy = 0.f;
            for (int ch = 0; ch < nch; ch++) {
                size_t base = ((size_t)ch * l + j) * SEQ + s;
                float2 a = g_pud[base]; udx += a.x; udy += a.y;
                float2 c = g_pus[base]; usx += c.x; usy += c.y;
            }
            if (!cj) {
                if (j == 0 || 2 * j == m) Z = make_float2(udx, usx);  // DC/Nyquist: real parts only
                else                      Z = make_float2(udx - usy, udy + usx);
            } else {
                Z = make_float2(udx + usy, usx - udy);                 // conj(Gd) + i*conj(Gs)
            }
        }
        int r = logm ? (int)(__brev((unsigned)k) >> (32 - logm)) : 0;
        sb[r] = Z;
    }
    __syncthreads();
    fft_sm<1>(sb, m, logm);
    float inv = 1.0f / (float)m;
    float* pud = g_Ud + off + (size_t)s * m;
    float* pus = g_Us + off + (size_t)s * m;
    for (int t = threadIdx.x; t < m; t += T) {
        float2 v = sb[t];
        pud[t] = v.x * inv;
        pus[t] = v.y * inv;
    }
}

// ---------------- coarsest-scale T0 linear map ----------------
__global__ void k_t0(const float* __restrict__ xin, const float* __restrict__ w,
                     const float* __restrict__ bias, float* __restrict__ out) {
    int id = blockIdx.x * blockDim.x + threadIdx.x;
    if (id >= 512) return;
    float v[4];
    #pragma unroll
    for (int k = 0; k < 4; k++) v[k] = xin[id * 4 + k];
    #pragma unroll
    for (int kp = 0; kp < 4; kp++) {
        float a = __ldg(&bias[kp]);
        #pragma unroll
        for (int k = 0; k < 4; k++) a += v[k] * __ldg(&w[kp * 4 + k]);
        out[id * 4 + kp] = a;
    }
}

// ---------------- reconstruction: x += Us; [x|Ud] @ rc_e / rc_o, interleave ----------------
__global__ void k_rec(const float* __restrict__ rin, int m, size_t off,
                      float* __restrict__ rout, int final_,
                      const float* __restrict__ rce, const float* __restrict__ rco) {
    int id = blockIdx.x * blockDim.x + threadIdx.x;
    if (id >= 512 * m) return;
    int t = id % m;
    int bc = id / m;
    int row0 = bc * 4;
    float xs[4], ud[4];
    #pragma unroll
    for (int k = 0; k < 4; k++) {
        size_t o = (size_t)(row0 + k) * m + t;
        xs[k] = rin[o] + g_Us[off + o];
        ud[k] = g_Ud[off + o];
    }
    float ev[4], ov[4];
    #pragma unroll
    for (int kp = 0; kp < 4; kp++) {
        float e = 0.f, o = 0.f;
        #pragma unroll
        for (int j = 0; j < 4; j++) {
            e += xs[j] * __ldg(&rce[j * 4 + kp]) + ud[j] * __ldg(&rce[(4 + j) * 4 + kp]);
            o += xs[j] * __ldg(&rco[j * 4 + kp]) + ud[j] * __ldg(&rco[(4 + j) * 4 + kp]);
        }
        ev[kp] = e; ov[kp] = o;
    }
    if (final_) {
        int b = bc >> 5, c = bc & 31;
        float* p0 = rout + (((size_t)b * NSEQ + 2 * t) * 32 + c) * 4;
        float* p1 = p0 + 128;
        #pragma unroll
        for (int kp = 0; kp < 4; kp++) { p0[kp] = ev[kp]; p1[kp] = ov[kp]; }
    } else {
        #pragma unroll
        for (int kp = 0; kp < 4; kp++) {
            size_t o = (size_t)(row0 + kp) * (2 * m);
            rout[o + 2 * t]     = ev[kp];
            rout[o + 2 * t + 1] = ov[kp];
        }
    }
}

// ---------------- host orchestration ----------------
extern "C" void kernel_launch(void* const* d_in, const int* in_sizes, int n_in,
                              void* d_out, int out_size) {
    const float* x   = (const float*)d_in[0];
    const float* wAr = (const float*)d_in[1];
    const float* wAi = (const float*)d_in[2];
    const float* wBr = (const float*)d_in[3];
    const float* wBi = (const float*)d_in[4];
    const float* wCr = (const float*)d_in[5];
    const float* wCi = (const float*)d_in[6];
    const float* ecs = (const float*)d_in[7];
    const float* ecd = (const float*)d_in[8];
    const float* rce = (const float*)d_in[9];
    const float* rco = (const float*)d_in[10];
    const float* t0w = (const float*)d_in[11];
    const float* t0b = (const float*)d_in[12];
    float* out = (float*)d_out;

    float *p_xt, *p_x0, *p_x1; float2* p_z;
    cudaGetSymbolAddress((void**)&p_xt, g_xt);
    cudaGetSymbolAddress((void**)&p_x0, g_x0);
    cudaGetSymbolAddress((void**)&p_x1, g_x1);
    cudaGetSymbolAddress((void**)&p_z,  g_z);

    k_tw<<<8, 256>>>();
    k_tin<<<16 * 256, 256>>>(x);
    k_wt<<<dim3(16, 128, 6), dim3(32, 8)>>>(wAr, wAi, wBr, wBi, wCr, wCi);

    size_t cum = 0;
    for (int lev = 0; lev < 13; lev++) {
        int m = (NSEQ >> lev) >> 1;
        int logm = 12 - lev;
        int l = (m / 2 + 1 < 128) ? (m / 2 + 1) : 128;
        const float* xin = (lev == 0) ? p_xt : ((lev & 1) ? p_x0 : p_x1);
        float* xnext = (lev & 1) ? p_x1 : p_x0;

        int tot = 512 * m;
        k_dec<<<(tot + 255) / 256, 256>>>(xin, m, xnext, ecs, ecd);

        int T = (m >= 1024) ? 512 : ((m >= 64) ? (m >> 1) : 32);
        k_fftf<<<SEQ, T, m * sizeof(float2)>>>(m, logm, l);

        int nch = (l >= 32) ? 4 : 16;
        int ilen = 128 / nch;
        k_mix<<<dim3(l, nch), 128>>>(l, ilen);

        k_ffti<<<SEQ, T, m * sizeof(float2)>>>(m, logm, l, nch, cum * (size_t)SEQ);
        cum += m;
    }

    // coarsest x (length 1) lives in g_x0 (written by level 12)
    k_t0<<<2, 256>>>(p_x0, t0w, t0b, p_xt);

    float* bufA = p_xt;
    float* bufB = (float*)p_z;
    float* cur = bufA;
    for (int lev = 12; lev >= 0; lev--) {
        int m = (NSEQ >> lev) >> 1;
        cum -= m;
        size_t off = cum * (size_t)SEQ;
        int fin = (lev == 0);
        float* rout = fin ? out : ((cur == bufA) ? bufB : bufA);
        int tot = 512 * m;
        k_rec<<<(tot + 255) / 256, 256>>>(cur, m, off, rout, fin, rce, rco);
        if (!fin) cur = rout;
    }
    (void)in_sizes; (void)n_in; (void)out_size;
}

// round 8
// speedup vs baseline: 1.4811x; 1.4811x over previous
#include <cuda_runtime.h>

#define SEQ   2048          // B * CK
#define CKD   128
#define NSEQ  8192
#define W3    (128*128*128)

// ---------------- static device scratch (no allocations allowed) ----------------
__device__ float  g_xt[SEQ * NSEQ];      // transposed input x0 (B,CK,N); later recon buf A
__device__ float2 g_z  [SEQ * 4096];     // packed d + i*s per level; later recon buf B
__device__ float  g_x0 [SEQ * 4096];     // smooth coeffs, odd levels (x1, x3, ...)
__device__ float  g_x1 [SEQ * 2048];     // smooth coeffs, even levels (x2, x4, ...)
__device__ float2 g_Df [128 * SEQ];      // (mode, b, i) spectra of d
__device__ float2 g_Sf [128 * SEQ];      // (mode, b, i) spectra of s
__device__ float2 g_pud[512 * SEQ];      // partial UdF per i-chunk
__device__ float2 g_pus[512 * SEQ];      // partial UsF per i-chunk
__device__ float  g_wt [6 * W3];         // weights transposed to (w, mode, i, o)
__device__ float  g_Ud [SEQ * 8191];     // stored detail outputs, all levels
__device__ float  g_Us [SEQ * 8191];     // stored smooth outputs, all levels
__device__ float2 g_tw [2048];           // tw[x] = exp(-2*pi*i*x/4096), x < 2048

// ---------------- complex helpers ----------------
__device__ __forceinline__ float2 cadd(float2 a, float2 b){ return make_float2(a.x+b.x, a.y+b.y); }
__device__ __forceinline__ float2 csub(float2 a, float2 b){ return make_float2(a.x-b.x, a.y-b.y); }
__device__ __forceinline__ float2 cmul(float2 a, float2 b){
    return make_float2(fmaf(a.x, b.x, -a.y*b.y), fmaf(a.x, b.y, a.y*b.x));
}
__device__ __forceinline__ float2 cconj(float2 a){ return make_float2(a.x, -a.y); }
// e^{-2*pi*i*x/4096}, x in [0,4096)
__device__ __forceinline__ float2 lut4096(int x){
    float2 t = __ldg(&g_tw[x & 2047]);
    if (x & 2048) { t.x = -t.x; t.y = -t.y; }
    return t;
}

// ---------------- twiddle table (built once per call, precise sincosf) ----------------
__global__ void k_tw() {
    int x = blockIdx.x * blockDim.x + threadIdx.x;
    if (x >= 2048) return;
    float ang = -6.283185307179586f * (float)x / 4096.0f;
    float s, c;
    sincosf(ang, &s, &c);
    g_tw[x] = make_float2(c, s);
}

// ---------------- input transpose: (B,N,C,K) -> (B, CK, N) ----------------
__global__ void k_tin(const float* __restrict__ x) {
    __shared__ float tile[32][129];
    int b  = blockIdx.x >> 8;
    int n0 = (blockIdx.x & 255) << 5;
    const float* src = x + ((size_t)b * NSEQ + n0) * CKD;
    for (int idx = threadIdx.x; idx < 32 * 128; idx += blockDim.x) {
        int r = idx >> 7, cc = idx & 127;
        tile[r][cc] = src[(size_t)r * CKD + cc];
    }
    __syncthreads();
    float* dst = g_xt + (size_t)b * CKD * NSEQ + n0;
    for (int idx = threadIdx.x; idx < 32 * 128; idx += blockDim.x) {
        int ck = idx >> 5, j = idx & 31;
        dst[(size_t)ck * NSEQ + j] = tile[j][ck];
    }
}

// ---------------- weight transpose: (i,o,mode) -> (mode,i,o), per weight w ----------------
__global__ void k_wt(const float* __restrict__ wAr, const float* __restrict__ wAi,
                     const float* __restrict__ wBr, const float* __restrict__ wBi,
                     const float* __restrict__ wCr, const float* __restrict__ wCi) {
    __shared__ float tile[32][33];
    int w = blockIdx.z;
    int i = blockIdx.y;
    int ot = (blockIdx.x >> 2) << 5;
    int mt = (blockIdx.x & 3) << 5;
    const float* src;
    switch (w) {
        case 0: src = wAr; break; case 1: src = wAi; break;
        case 2: src = wBr; break; case 3: src = wBi; break;
        case 4: src = wCr; break; default: src = wCi; break;
    }
    int tx = threadIdx.x, ty = threadIdx.y;
    #pragma unroll
    for (int j = 0; j < 32; j += 8)
        tile[ty + j][tx] = src[((size_t)i * 128 + ot + ty + j) * 128 + mt + tx];
    __syncthreads();
    float* dst = g_wt + (size_t)w * W3;
    #pragma unroll
    for (int j = 0; j < 32; j += 8)
        dst[((size_t)(mt + ty + j) * 128 + i) * 128 + ot + tx] = tile[tx][ty + j];
}

// ---------------- decompose: filter bank + pack z = d + i*s ----------------
__global__ void k_dec(const float* __restrict__ xin, int m,
                      float* __restrict__ xnext,
                      const float* __restrict__ ecs, const float* __restrict__ ecd) {
    int id = blockIdx.x * blockDim.x + threadIdx.x;
    if (id >= 512 * m) return;
    int t = id % m;
    int bc = id / m;
    int row0 = bc * 4;
    int n = 2 * m;
    float xa[8];
    #pragma unroll
    for (int k = 0; k < 4; k++) {
        const float* p = xin + (size_t)(row0 + k) * n + 2 * t;
        xa[k]     = p[0];
        xa[4 + k] = p[1];
    }
    #pragma unroll
    for (int kp = 0; kp < 4; kp++) {
        float d = 0.f, s = 0.f;
        #pragma unroll
        for (int j = 0; j < 8; j++) {
            d += xa[j] * __ldg(&ecd[j * 4 + kp]);
            s += xa[j] * __ldg(&ecs[j * 4 + kp]);
        }
        size_t o = (size_t)(row0 + kp) * m + t;
        g_z[o] = make_float2(d, s);
        xnext[o] = s;
    }
}

// ================= register-resident warp FFT-128 (DIF, output bit-reversed) ==========
struct Tw7 { float2 wA, wB, w32, w16, w8, w4, w2; };

__device__ __forceinline__ Tw7 make_tw7(int L) {
    Tw7 t;
    t.wA  = __ldg(&g_tw[L * 32]);          // W128^L
    t.wB  = __ldg(&g_tw[(L + 32) * 32]);   // W128^{L+32}
    t.w32 = __ldg(&g_tw[L * 64]);          // W128^{2L}
    t.w16 = __ldg(&g_tw[(L & 15) * 128]);  // W32^{L&15}
    t.w8  = __ldg(&g_tw[(L & 7) * 256]);   // W16^{L&7}
    t.w4  = __ldg(&g_tw[(L & 3) * 512]);   // W8^{L&3}
    t.w2  = __ldg(&g_tw[(L & 1) * 1024]);  // W4^{L&1}
    return t;
}

__device__ __forceinline__ void cross_stage(float2& x, int bit, float2 w, int L) {
    float ox = __shfl_xor_sync(0xFFFFFFFFu, x.x, bit);
    float oy = __shfl_xor_sync(0xFFFFFFFFu, x.y, bit);
    if (L & bit) x = cmul(make_float2(ox - x.x, oy - x.y), w);
    else         x = make_float2(x.x + ox, x.y + oy);
}
__device__ __forceinline__ void cross_last(float2& x, int L) {
    float ox = __shfl_xor_sync(0xFFFFFFFFu, x.x, 1);
    float oy = __shfl_xor_sync(0xFFFFFFFFu, x.y, 1);
    if (L & 1) x = make_float2(ox - x.x, oy - x.y);
    else       x = make_float2(x.x + ox, x.y + oy);
}

// v[j] holds element index 32*j + L (natural order in). After: pos p=32j+L holds X[rev7(p)].
__device__ __forceinline__ void fft128(float2 v[4], const Tw7& tw, int L) {
    float2 a, b;
    a = v[0]; b = v[2]; v[0] = cadd(a, b); v[2] = cmul(csub(a, b), tw.wA);
    a = v[1]; b = v[3]; v[1] = cadd(a, b); v[3] = cmul(csub(a, b), tw.wB);
    a = v[0]; b = v[1]; v[0] = cadd(a, b); v[1] = cmul(csub(a, b), tw.w32);
    a = v[2]; b = v[3]; v[2] = cadd(a, b); v[3] = cmul(csub(a, b), tw.w32);
    #pragma unroll
    for (int j = 0; j < 4; j++) cross_stage(v[j], 16, tw.w16, L);
    #pragma unroll
    for (int j = 0; j < 4; j++) cross_stage(v[j], 8, tw.w8, L);
    #pragma unroll
    for (int j = 0; j < 4; j++) cross_stage(v[j], 4, tw.w4, L);
    #pragma unroll
    for (int j = 0; j < 4; j++) cross_stage(v[j], 2, tw.w2, L);
    #pragma unroll
    for (int j = 0; j < 4; j++) cross_last(v[j], L);
}

// ---------------- pruned forward: m = 128*M, only modes k<128 and m-k needed ----------
template<int M>
__global__ void __launch_bounds__(256) k_pfwd() {
    constexpr int m = 128 * M;
    constexpr int R = 32 / M;            // 4096/m
    extern __shared__ float2 sm[];
    float2* xin  = sm;                   // m + m/32 (padded)
    float2* ybuf = sm + m + (m >> 5);    // m, natural bin order [t2][q]
    int s = blockIdx.x;
    int tid = threadIdx.x, L = tid & 31, w = tid >> 5;

    const float2* src = g_z + (size_t)s * m;
    for (int t = tid; t < m; t += 256) xin[t + (t >> 5)] = src[t];
    Tw7 tw = make_tw7(L);
    __syncthreads();

    const int rounds = M >> 3;           // M in {8,16,32} -> 1,2,4
    for (int r = 0; r < rounds; r++) {
        int t2 = (r << 3) + w;
        float2 v[4];
        #pragma unroll
        for (int j = 0; j < 4; j++) {
            int t = M * (32 * j + L) + t2;
            v[j] = xin[t + (t >> 5)];
        }
        fft128(v, tw, L);
        #pragma unroll
        for (int j = 0; j < 4; j++) {
            int p = 32 * j + L;
            int q = (int)(__brev((unsigned)p) >> 25);     // de-bit-reverse on store
            ybuf[t2 * 128 + q] = v[j];
        }
    }
    __syncthreads();

    if (tid < 128) {
        int k = tid;
        int k2 = (128 - k) & 127;
        float2 Xk = make_float2(0.f, 0.f), Xm = make_float2(0.f, 0.f);
        int step = k * R;
        int idx = 0;
        for (int t2 = 0; t2 < M; t2++) {
            float2 wtw = lut4096(idx);                    // e^{-2pi i k t2 / m}
            Xk = cadd(Xk, cmul(wtw, ybuf[t2 * 128 + k]));
            Xm = cadd(Xm, cmul(cconj(wtw), ybuf[t2 * 128 + k2]));
            idx = (idx + step) & 4095;
        }
        float2 Df = make_float2(0.5f * (Xk.x + Xm.x), 0.5f * (Xk.y - Xm.y));
        float2 Sf = make_float2(0.5f * (Xk.y + Xm.y), 0.5f * (Xm.x - Xk.x));
        g_Df[(size_t)k * SEQ + s] = Df;
        g_Sf[(size_t)k * SEQ + s] = Sf;
    }
}

// ---------------- pruned inverse: bins j<128 and m-j, fold + M x IFFT128 --------------
template<int M>
__global__ void __launch_bounds__(256) k_pinv(int nch, size_t off) {
    constexpr int m = 128 * M;
    constexpr int R = 32 / M;
    extern __shared__ float2 sm[];
    float2* zbuf  = sm;              // 128
    float2* zmbuf = sm + 128;        // 128
    float2* obuf  = sm + 256;        // m + m/32 (padded)
    int s = blockIdx.x;
    int tid = threadIdx.x, L = tid & 31, w = tid >> 5;

    if (tid < 128) {
        int j = tid;
        float udx = 0.f, udy = 0.f, usx = 0.f, usy = 0.f;
        for (int ch = 0; ch < nch; ch++) {
            size_t base = ((size_t)ch * 128 + j) * SEQ + s;
            float2 a = g_pud[base]; udx += a.x; udy += a.y;
            float2 c = g_pus[base]; usx += c.x; usy += c.y;
        }
        if (j == 0) {
            zbuf[0]  = make_float2(udx, usx);      // DC: drop imag parts
            zmbuf[0] = make_float2(0.f, 0.f);
        } else {
            zbuf[j]  = make_float2(udx - usy, udy + usx);   // Z[j]
            zmbuf[j] = make_float2(udx + usy, usx - udy);   // Z[m-j]
        }
    }
    Tw7 tw = make_tw7(L);
    __syncthreads();

    const int rounds = M >> 3;
    for (int r = 0; r < rounds; r++) {
        int t2 = (r << 3) + w;
        float2 f  = lut4096(t2 * (4096 / M));      // e^{-2pi i t2/M}
        float2 cf = cconj(f);
        float2 v[4];
        #pragma unroll
        for (int j = 0; j < 4; j++) {
            int q = 32 * j + L;
            float2 cZ  = cconj(zbuf[q]);
            float2 cZm = cconj(zmbuf[(128 - q) & 127]);
            float2 t   = cadd(cZ, cmul(cf, cZm));
            v[j] = cmul(lut4096((q * t2 * R) & 4095), t);   // conj(e1^q)
        }
        fft128(v, tw, L);
        const float inv = 1.0f / (float)m;
        #pragma unroll
        for (int j = 0; j < 4; j++) {
            int p = 32 * j + L;
            int u = (int)(__brev((unsigned)p) >> 25);
            int t = M * u + t2;
            obuf[t + (t >> 5)] = make_float2(v[j].x * inv, -v[j].y * inv);  // conj/m
        }
    }
    __syncthreads();

    float* pud = g_Ud + off + (size_t)s * m;
    float* pus = g_Us + off + (size_t)s * m;
    for (int t = tid; t < m; t += 256) {
        float2 vv = obuf[t + (t >> 5)];
        pud[t] = vv.x;
        pus[t] = vv.y;
    }
}

// ---------------- old shared-mem FFT path (R3 config, small levels) ----------------
__device__ __forceinline__ void fft_sm(float2* sb, int m, int logm, float sgn) {
    int T = blockDim.x;
    for (int st = 1; st <= logm; st++) {
        int half = 1 << (st - 1);
        float scale = sgn * 6.283185307179586f / (float)(1 << st);
        for (int idx = threadIdx.x; idx < (m >> 1); idx += T) {
            int j = idx & (half - 1);
            int pos = ((idx >> (st - 1)) << st) + j;
            float sw, cw;
            sincosf(scale * (float)j, &sw, &cw);
            float2 u = sb[pos], v = sb[pos + half];
            float2 tv = make_float2(v.x * cw - v.y * sw, v.x * sw + v.y * cw);
            sb[pos]        = make_float2(u.x + tv.x, u.y + tv.y);
            sb[pos + half] = make_float2(u.x - tv.x, u.y - tv.y);
        }
        __syncthreads();
    }
}

__global__ void k_fftf(int m, int logm, int l) {
    extern __shared__ float2 sb[];
    int s = blockIdx.x;
    int T = blockDim.x;
    const float2* zin = g_z + (size_t)s * m;
    for (int t = threadIdx.x; t < m; t += T) {
        int r = logm ? (int)(__brev((unsigned)t) >> (32 - logm)) : 0;
        sb[r] = zin[t];
    }
    __syncthreads();
    fft_sm(sb, m, logm, -1.0f);
    for (int k = threadIdx.x; k < l; k += T) {
        float2 Zk = sb[k];
        float2 Zm = sb[(m - k) & (m - 1)];
        float2 Df = make_float2(0.5f * (Zk.x + Zm.x), 0.5f * (Zk.y - Zm.y));
        float2 Sf = make_float2(0.5f * (Zk.y + Zm.y), 0.5f * (Zm.x - Zk.x));
        g_Df[(size_t)k * SEQ + s] = Df;
        g_Sf[(size_t)k * SEQ + s] = Sf;
    }
}

// ---------------- per-mode complex channel mixing (partial over i-chunk) ----------------
__global__ void __launch_bounds__(128) k_mix(int l, int ilen) {
    __shared__ float2 sdf[16][32], ssf[16][32];
    int mode = blockIdx.x, ch = blockIdx.y;
    int i0 = ch * ilen;
    int cnt = 16 * ilen;
    for (int idx = threadIdx.x; idx < cnt; idx += 128) {
        int bb = idx / ilen, ii = idx - bb * ilen;
        size_t src = (size_t)mode * SEQ + bb * 128 + i0 + ii;
        sdf[bb][ii] = g_Df[src];
        ssf[bb][ii] = g_Sf[src];
    }
    __syncthreads();
    int o = threadIdx.x;
    float udr[16], udi[16], usr[16], usi[16];
    #pragma unroll
    for (int b = 0; b < 16; b++) { udr[b] = udi[b] = usr[b] = usi[b] = 0.f; }
    for (int ii = 0; ii < ilen; ii++) {
        size_t widx = ((size_t)mode * 128 + (i0 + ii)) * 128 + o;
        float ar = g_wt[widx],          ai = g_wt[W3 + widx];
        float br = g_wt[2 * W3 + widx], bi = g_wt[3 * W3 + widx];
        float cr = g_wt[4 * W3 + widx], ci = g_wt[5 * W3 + widx];
        #pragma unroll
        for (int b = 0; b < 16; b++) {
            float2 df = sdf[b][ii], sf = ssf[b][ii];
            udr[b] += df.x * ar - df.y * ai + sf.x * br - sf.y * bi;
            udi[b] += df.x * ai + df.y * ar + sf.x * bi + sf.y * br;
            usr[b] += df.x * cr - df.y * ci;
            usi[b] += df.x * ci + df.y * cr;
        }
    }
    size_t base = ((size_t)ch * l + mode) * SEQ + o;
    #pragma unroll
    for (int b = 0; b < 16; b++) {
        g_pud[base + b * 128] = make_float2(udr[b], udi[b]);
        g_pus[base + b * 128] = make_float2(usr[b], usi[b]);
    }
}

// ---------------- old inverse FFT (small levels) ----------------
__global__ void k_ffti(int m, int logm, int l, int nch, size_t off) {
    extern __shared__ float2 sb[];
    int s = blockIdx.x;
    int T = blockDim.x;
    for (int k = threadIdx.x; k < m; k += T) {
        float2 Z = make_float2(0.f, 0.f);
        int j = -1, cj = 0;
        if (k < l) { j = k; }
        else { int jm = m - k; if (jm < l) { j = jm; cj = 1; } }
        if (j >= 0) {
            float udx = 0.f, udy = 0.f, usx = 0.f, usy = 0.f;
            for (int ch = 0; ch < nch; ch++) {
                size_t base = ((size_t)ch * l + j) * SEQ + s;
                float2 a = g_pud[base]; udx += a.x; udy += a.y;
                float2 c = g_pus[base]; usx += c.x; usy += c.y;
            }
            if (!cj) {
                if (j == 0 || 2 * j == m) Z = make_float2(udx, usx);
                else                      Z = make_float2(udx - usy, udy + usx);
            } else {
                Z = make_float2(udx + usy, usx - udy);
            }
        }
        int r = logm ? (int)(__brev((unsigned)k) >> (32 - logm)) : 0;
        sb[r] = Z;
    }
    __syncthreads();
    fft_sm(sb, m, logm, +1.0f);
    float inv = 1.0f / (float)m;
    float* pud = g_Ud + off + (size_t)s * m;
    float* pus = g_Us + off + (size_t)s * m;
    for (int t = threadIdx.x; t < m; t += T) {
        float2 v = sb[t];
        pud[t] = v.x * inv;
        pus[t] = v.y * inv;
    }
}

// ---------------- coarsest-scale T0 linear map ----------------
__global__ void k_t0(const float* __restrict__ xin, const float* __restrict__ w,
                     const float* __restrict__ bias, float* __restrict__ out) {
    int id = blockIdx.x * blockDim.x + threadIdx.x;
    if (id >= 512) return;
    float v[4];
    #pragma unroll
    for (int k = 0; k < 4; k++) v[k] = xin[id * 4 + k];
    #pragma unroll
    for (int kp = 0; kp < 4; kp++) {
        float a = __ldg(&bias[kp]);
        #pragma unroll
        for (int k = 0; k < 4; k++) a += v[k] * __ldg(&w[kp * 4 + k]);
        out[id * 4 + kp] = a;
    }
}

// ---------------- reconstruction ----------------
__global__ void k_rec(const float* __restrict__ rin, int m, size_t off,
                      float* __restrict__ rout, int final_,
                      const float* __restrict__ rce, const float* __restrict__ rco) {
    int id = blockIdx.x * blockDim.x + threadIdx.x;
    if (id >= 512 * m) return;
    int t = id % m;
    int bc = id / m;
    int row0 = bc * 4;
    float xs[4], ud[4];
    #pragma unroll
    for (int k = 0; k < 4; k++) {
        size_t o = (size_t)(row0 + k) * m + t;
        xs[k] = rin[o] + g_Us[off + o];
        ud[k] = g_Ud[off + o];
    }
    float ev[4], ov[4];
    #pragma unroll
    for (int kp = 0; kp < 4; kp++) {
        float e = 0.f, o = 0.f;
        #pragma unroll
        for (int j = 0; j < 4; j++) {
            e += xs[j] * __ldg(&rce[j * 4 + kp]) + ud[j] * __ldg(&rce[(4 + j) * 4 + kp]);
            o += xs[j] * __ldg(&rco[j * 4 + kp]) + ud[j] * __ldg(&rco[(4 + j) * 4 + kp]);
        }
        ev[kp] = e; ov[kp] = o;
    }
    if (final_) {
        int b = bc >> 5, c = bc & 31;
        float* p0 = rout + (((size_t)b * NSEQ + 2 * t) * 32 + c) * 4;
        float* p1 = p0 + 128;
        #pragma unroll
        for (int kp = 0; kp < 4; kp++) { p0[kp] = ev[kp]; p1[kp] = ov[kp]; }
    } else {
        #pragma unroll
        for (int kp = 0; kp < 4; kp++) {
            size_t o = (size_t)(row0 + kp) * (2 * m);
            rout[o + 2 * t]     = ev[kp];
            rout[o + 2 * t + 1] = ov[kp];
        }
    }
}

// ---------------- host orchestration ----------------
extern "C" void kernel_launch(void* const* d_in, const int* in_sizes, int n_in,
                              void* d_out, int out_size) {
    const float* x   = (const float*)d_in[0];
    const float* wAr = (const float*)d_in[1];
    const float* wAi = (const float*)d_in[2];
    const float* wBr = (const float*)d_in[3];
    const float* wBi = (const float*)d_in[4];
    const float* wCr = (const float*)d_in[5];
    const float* wCi = (const float*)d_in[6];
    const float* ecs = (const float*)d_in[7];
    const float* ecd = (const float*)d_in[8];
    const float* rce = (const float*)d_in[9];
    const float* rco = (const float*)d_in[10];
    const float* t0w = (const float*)d_in[11];
    const float* t0b = (const float*)d_in[12];
    float* out = (float*)d_out;

    float *p_xt, *p_x0, *p_x1; float2* p_z;
    cudaGetSymbolAddress((void**)&p_xt, g_xt);
    cudaGetSymbolAddress((void**)&p_x0, g_x0);
    cudaGetSymbolAddress((void**)&p_x1, g_x1);
    cudaGetSymbolAddress((void**)&p_z,  g_z);

    // opt-in > 48KB dynamic smem for the big pruned-forward kernel (idempotent)
    cudaFuncSetAttribute(k_pfwd<32>, cudaFuncAttributeMaxDynamicSharedMemorySize, 70000);

    k_tw<<<8, 256>>>();
    k_tin<<<16 * 256, 256>>>(x);
    k_wt<<<dim3(16, 128, 6), dim3(32, 8)>>>(wAr, wAi, wBr, wBi, wCr, wCi);

    size_t cum = 0;
    for (int lev = 0; lev < 13; lev++) {
        int m = (NSEQ >> lev) >> 1;
        int logm = 12 - lev;
        int l = (m / 2 + 1 < 128) ? (m / 2 + 1) : 128;
        const float* xin = (lev == 0) ? p_xt : ((lev & 1) ? p_x0 : p_x1);
        float* xnext = (lev & 1) ? p_x1 : p_x0;

        int tot = 512 * m;
        k_dec<<<(tot + 255) / 256, 256>>>(xin, m, xnext, ecs, ecd);

        int nch = (l >= 32) ? 4 : 16;
        int ilen = 128 / nch;

        if (lev <= 2) {
            int M = m / 128;                                  // 32, 16, 8
            size_t pfw = (size_t)(2 * m + m / 32) * sizeof(float2);
            size_t piv = (size_t)(256 + m + m / 32) * sizeof(float2);
            if (M == 32)      k_pfwd<32><<<SEQ, 256, pfw>>>();
            else if (M == 16) k_pfwd<16><<<SEQ, 256, pfw>>>();
            else              k_pfwd<8> <<<SEQ, 256, pfw>>>();
            k_mix<<<dim3(l, nch), 128>>>(l, ilen);
            if (M == 32)      k_pinv<32><<<SEQ, 256, piv>>>(nch, cum * (size_t)SEQ);
            else if (M == 16) k_pinv<16><<<SEQ, 256, piv>>>(nch, cum * (size_t)SEQ);
            else              k_pinv<8> <<<SEQ, 256, piv>>>(nch, cum * (size_t)SEQ);
        } else {
            int T = (m >= 512) ? 256 : ((m >= 64) ? (m >> 1) : 32);
            k_fftf<<<SEQ, T, m * sizeof(float2)>>>(m, logm, l);
            k_mix<<<dim3(l, nch), 128>>>(l, ilen);
            k_ffti<<<SEQ, T, m * sizeof(float2)>>>(m, logm, l, nch, cum * (size_t)SEQ);
        }
        cum += m;
    }

    k_t0<<<2, 256>>>(p_x0, t0w, t0b, p_xt);

    float* bufA = p_xt;
    float* bufB = (float*)p_z;
    float* cur = bufA;
    for (int lev = 12; lev >= 0; lev--) {
        int m = (NSEQ >> lev) >> 1;
        cum -= m;
        size_t off = cum * (size_t)SEQ;
        int fin = (lev == 0);
        float* rout = fin ? out : ((cur == bufA) ? bufB : bufA);
        int tot = 512 * m;
        k_rec<<<(tot + 255) / 256, 256>>>(cur, m, off, rout, fin, rce, rco);
        if (!fin) cur = rout;
    }
    (void)in_sizes; (void)n_in; (void)out_size;
}

// round 9
// speedup vs baseline: 1.7781x; 1.2005x over previous
#include <cuda_runtime.h>

#define SEQ   2048          // B * CK
#define CKD   128
#define NSEQ  8192
#define W3    (128*128*128)

// ---------------- static device scratch (no allocations allowed) ----------------
__device__ float  g_xt[SEQ * NSEQ];       // transposed input x0 (B,CK,N); later recon buf A
__device__ float2 g_z  [SEQ * 4096];      // recon buf B
__device__ float2 g_zall[SEQ * 8191];     // packed d + i*s, ALL levels (offsets c_zoff)
__device__ float  g_x0 [SEQ * 4096];      // smooth coeffs ping
__device__ float  g_x1 [SEQ * 2048];      // smooth coeffs pong
__device__ float2 g_Df [775 * SEQ];       // (global mode, s) spectra of d, all levels
__device__ float2 g_Sf [775 * SEQ];       // (global mode, s) spectra of s
__device__ float2 g_pud[3544 * SEQ];      // partial UdF, all levels (offsets c_pudoff)
__device__ float2 g_pus[3544 * SEQ];      // partial UsF
__device__ float  g_wt [6 * W3];          // weights transposed to (w, mode, i, o)
__device__ float  g_Ud [SEQ * 8191];      // detail outputs, all levels
__device__ float  g_Us [SEQ * 8191];      // smooth outputs, all levels
__device__ float2 g_tw [2048];            // tw[x] = exp(-2*pi*i*x/4096)

// ---------------- per-level compile-time tables ----------------
__constant__ int c_l[13]       = {128,128,128,128,128,65,33,17,9,5,3,2,1};
__constant__ int c_nch[13]     = {4,4,4,4,4,4,4,16,16,16,16,16,16};
__constant__ int c_modeoff[13] = {0,128,256,384,512,640,705,738,755,764,769,772,774};
__constant__ int c_pudoff[13]  = {0,512,1024,1536,2048,2560,2820,2952,3224,3368,3448,3496,3528};
__constant__ int c_mixblk[14]  = {0,512,1024,1536,2048,2560,2820,2952,3224,3368,3448,3496,3528,3544};
__constant__ int c_zoff[13]    = {0,4096,6144,7168,7680,7936,8064,8128,8160,8176,8184,8188,8190};

static const int h_l[13]       = {128,128,128,128,128,65,33,17,9,5,3,2,1};
static const int h_nch[13]     = {4,4,4,4,4,4,4,16,16,16,16,16,16};
static const int h_modeoff[13] = {0,128,256,384,512,640,705,738,755,764,769,772,774};
static const int h_pudoff[13]  = {0,512,1024,1536,2048,2560,2820,2952,3224,3368,3448,3496,3528};
static const int h_zoff[13]    = {0,4096,6144,7168,7680,7936,8064,8128,8160,8176,8184,8188,8190};

// ---------------- complex helpers ----------------
__device__ __forceinline__ float2 cadd(float2 a, float2 b){ return make_float2(a.x+b.x, a.y+b.y); }
__device__ __forceinline__ float2 csub(float2 a, float2 b){ return make_float2(a.x-b.x, a.y-b.y); }
__device__ __forceinline__ float2 cmul(float2 a, float2 b){
    return make_float2(fmaf(a.x, b.x, -a.y*b.y), fmaf(a.x, b.y, a.y*b.x));
}
__device__ __forceinline__ float2 cconj(float2 a){ return make_float2(a.x, -a.y); }
__device__ __forceinline__ float2 lut4096(int x){
    float2 t = __ldg(&g_tw[x & 2047]);
    if (x & 2048) { t.x = -t.x; t.y = -t.y; }
    return t;
}

// ---------------- twiddle table ----------------
__global__ void k_tw() {
    int x = blockIdx.x * blockDim.x + threadIdx.x;
    if (x >= 2048) return;
    float ang = -6.283185307179586f * (float)x / 4096.0f;
    float s, c;
    sincosf(ang, &s, &c);
    g_tw[x] = make_float2(c, s);
}

// ---------------- input transpose: (B,N,C,K) -> (B, CK, N) ----------------
__global__ void k_tin(const float* __restrict__ x) {
    __shared__ float tile[32][129];
    int b  = blockIdx.x >> 8;
    int n0 = (blockIdx.x & 255) << 5;
    const float* src = x + ((size_t)b * NSEQ + n0) * CKD;
    for (int idx = threadIdx.x; idx < 32 * 128; idx += blockDim.x) {
        int r = idx >> 7, cc = idx & 127;
        tile[r][cc] = src[(size_t)r * CKD + cc];
    }
    __syncthreads();
    float* dst = g_xt + (size_t)b * CKD * NSEQ + n0;
    for (int idx = threadIdx.x; idx < 32 * 128; idx += blockDim.x) {
        int ck = idx >> 5, j = idx & 31;
        dst[(size_t)ck * NSEQ + j] = tile[j][ck];
    }
}

// ---------------- weight transpose: (i,o,mode) -> (mode,i,o) ----------------
__global__ void k_wt(const float* __restrict__ wAr, const float* __restrict__ wAi,
                     const float* __restrict__ wBr, const float* __restrict__ wBi,
                     const float* __restrict__ wCr, const float* __restrict__ wCi) {
    __shared__ float tile[32][33];
    int w = blockIdx.z;
    int i = blockIdx.y;
    int ot = (blockIdx.x >> 2) << 5;
    int mt = (blockIdx.x & 3) << 5;
    const float* src;
    switch (w) {
        case 0: src = wAr; break; case 1: src = wAi; break;
        case 2: src = wBr; break; case 3: src = wBi; break;
        case 4: src = wCr; break; default: src = wCi; break;
    }
    int tx = threadIdx.x, ty = threadIdx.y;
    #pragma unroll
    for (int j = 0; j < 32; j += 8)
        tile[ty + j][tx] = src[((size_t)i * 128 + ot + ty + j) * 128 + mt + tx];
    __syncthreads();
    float* dst = g_wt + (size_t)w * W3;
    #pragma unroll
    for (int j = 0; j < 32; j += 8)
        dst[((size_t)(mt + ty + j) * 128 + i) * 128 + ot + tx] = tile[tx][ty + j];
}

// ---------------- decompose: filter bank + pack z = d + i*s ----------------
__global__ void k_dec(const float* __restrict__ xin, int m,
                      float* __restrict__ xnext, float2* __restrict__ zdst,
                      const float* __restrict__ ecs, const float* __restrict__ ecd) {
    int id = blockIdx.x * blockDim.x + threadIdx.x;
    if (id >= 512 * m) return;
    int t = id % m;
    int bc = id / m;
    int row0 = bc * 4;
    int n = 2 * m;
    float xa[8];
    #pragma unroll
    for (int k = 0; k < 4; k++) {
        const float* p = xin + (size_t)(row0 + k) * n + 2 * t;
        xa[k]     = p[0];
        xa[4 + k] = p[1];
    }
    #pragma unroll
    for (int kp = 0; kp < 4; kp++) {
        float d = 0.f, s = 0.f;
        #pragma unroll
        for (int j = 0; j < 8; j++) {
            d += xa[j] * __ldg(&ecd[j * 4 + kp]);
            s += xa[j] * __ldg(&ecs[j * 4 + kp]);
        }
        size_t o = (size_t)(row0 + kp) * m + t;
        zdst[o] = make_float2(d, s);
        xnext[o] = s;
    }
}

// ================= register-resident warp FFT-128 (DIF, output bit-reversed) ==========
struct Tw7 { float2 wA, wB, w32, w16, w8, w4, w2; };

__device__ __forceinline__ Tw7 make_tw7(int L) {
    Tw7 t;
    t.wA  = __ldg(&g_tw[L * 32]);
    t.wB  = __ldg(&g_tw[(L + 32) * 32]);
    t.w32 = __ldg(&g_tw[L * 64]);
    t.w16 = __ldg(&g_tw[(L & 15) * 128]);
    t.w8  = __ldg(&g_tw[(L & 7) * 256]);
    t.w4  = __ldg(&g_tw[(L & 3) * 512]);
    t.w2  = __ldg(&g_tw[(L & 1) * 1024]);
    return t;
}

__device__ __forceinline__ void cross_stage(float2& x, int bit, float2 w, int L) {
    float ox = __shfl_xor_sync(0xFFFFFFFFu, x.x, bit);
    float oy = __shfl_xor_sync(0xFFFFFFFFu, x.y, bit);
    if (L & bit) x = cmul(make_float2(ox - x.x, oy - x.y), w);
    else         x = make_float2(x.x + ox, x.y + oy);
}
__device__ __forceinline__ void cross_last(float2& x, int L) {
    float ox = __shfl_xor_sync(0xFFFFFFFFu, x.x, 1);
    float oy = __shfl_xor_sync(0xFFFFFFFFu, x.y, 1);
    if (L & 1) x = make_float2(ox - x.x, oy - x.y);
    else       x = make_float2(x.x + ox, x.y + oy);
}

__device__ __forceinline__ void fft128(float2 v[4], const Tw7& tw, int L) {
    float2 a, b;
    a = v[0]; b = v[2]; v[0] = cadd(a, b); v[2] = cmul(csub(a, b), tw.wA);
    a = v[1]; b = v[3]; v[1] = cadd(a, b); v[3] = cmul(csub(a, b), tw.wB);
    a = v[0]; b = v[1]; v[0] = cadd(a, b); v[1] = cmul(csub(a, b), tw.w32);
    a = v[2]; b = v[3]; v[2] = cadd(a, b); v[3] = cmul(csub(a, b), tw.w32);
    #pragma unroll
    for (int j = 0; j < 4; j++) cross_stage(v[j], 16, tw.w16, L);
    #pragma unroll
    for (int j = 0; j < 4; j++) cross_stage(v[j], 8, tw.w8, L);
    #pragma unroll
    for (int j = 0; j < 4; j++) cross_stage(v[j], 4, tw.w4, L);
    #pragma unroll
    for (int j = 0; j < 4; j++) cross_stage(v[j], 2, tw.w2, L);
    #pragma unroll
    for (int j = 0; j < 4; j++) cross_last(v[j], L);
}

// ---------------- pruned forward: m = 128*M, modes k<l (and m-k) --------------------
template<int M, int SPB>
__global__ void __launch_bounds__(256) k_pfwd(const float2* __restrict__ zin0,
                                              int modeoff, int l) {
    constexpr int m = 128 * M;
    constexpr int R = 32 / M;
    constexpr int PADM = m + (m >> 5);
    extern __shared__ float2 sm[];
    float2* xin  = sm;                   // SPB * PADM
    float2* ybuf = sm + SPB * PADM;      // SPB * m  (natural bin order [t2][q])
    int tid = threadIdx.x, L = tid & 31, w = tid >> 5;
    int sbase = blockIdx.x * SPB;

    for (int t = tid; t < SPB * m; t += 256) {
        int ss = t / m, tt = t - ss * m;
        xin[ss * PADM + tt + (tt >> 5)] = zin0[(size_t)(sbase + ss) * m + tt];
    }
    Tw7 tw = make_tw7(L);
    __syncthreads();

    #pragma unroll
    for (int r = 0; r < ((M + 7) >> 3); r++) {
        int ss = (M >= 8) ? 0 : (w / M);
        int t2 = (M >= 8) ? ((r << 3) + w) : (w - ss * M);
        float2 v[4];
        const float2* xb = xin + ss * PADM;
        #pragma unroll
        for (int j = 0; j < 4; j++) {
            int t = M * (32 * j + L) + t2;
            v[j] = xb[t + (t >> 5)];
        }
        fft128(v, tw, L);
        #pragma unroll
        for (int j = 0; j < 4; j++) {
            int p = 32 * j + L;
            int q = (int)(__brev((unsigned)p) >> 25);
            ybuf[ss * m + t2 * 128 + q] = v[j];
        }
    }
    __syncthreads();

    for (int p = tid; p < SPB * 128; p += 256) {
        int ss = p >> 7, k = p & 127;
        if (k >= l) continue;
        int k2 = (128 - k) & 127;
        const float2* yb = ybuf + ss * m;
        float2 Xk = make_float2(0.f, 0.f), Xm = make_float2(0.f, 0.f);
        int step = (k * R) & 4095;
        int idx = 0;
        for (int t2 = 0; t2 < M; t2++) {
            float2 wtw = lut4096(idx);                 // e^{-2pi i k t2 / m}
            Xk = cadd(Xk, cmul(wtw, yb[t2 * 128 + k]));
            Xm = cadd(Xm, cmul(cconj(wtw), yb[t2 * 128 + k2]));
            idx = (idx + step) & 4095;
        }
        int s = sbase + ss;
        float2 Df = make_float2(0.5f * (Xk.x + Xm.x), 0.5f * (Xk.y - Xm.y));
        float2 Sf = make_float2(0.5f * (Xk.y + Xm.y), 0.5f * (Xm.x - Xk.x));
        g_Df[(size_t)(modeoff + k) * SEQ + s] = Df;
        g_Sf[(size_t)(modeoff + k) * SEQ + s] = Sf;
    }
}

// ---------------- pruned inverse --------------------------------------------------
template<int M, int SPB>
__global__ void __launch_bounds__(256) k_pinv(int pudoff, int l, int nch, size_t uoff) {
    constexpr int m = 128 * M;
    constexpr int R = 32 / M;
    constexpr int PADM = m + (m >> 5);
    extern __shared__ float2 sm[];
    float2* zbuf  = sm;                  // SPB*128
    float2* zmbuf = sm + SPB * 128;      // SPB*128
    float2* obuf  = sm + SPB * 256;      // SPB*PADM
    int tid = threadIdx.x, L = tid & 31, w = tid >> 5;
    int sbase = blockIdx.x * SPB;

    for (int p = tid; p < SPB * 128; p += 256) {
        int ss = p >> 7, j = p & 127;
        int s = sbase + ss;
        float2 zb = make_float2(0.f, 0.f), zm = make_float2(0.f, 0.f);
        if (j < l) {
            float udx = 0.f, udy = 0.f, usx = 0.f, usy = 0.f;
            for (int ch = 0; ch < nch; ch++) {
                size_t base = (size_t)(pudoff + ch * l + j) * SEQ + s;
                float2 a = g_pud[base]; udx += a.x; udy += a.y;
                float2 c = g_pus[base]; usx += c.x; usy += c.y;
            }
            if (j == 0 || 2 * j == m) { zb = make_float2(udx, usx); }       // DC / Nyquist
            else { zb = make_float2(udx - usy, udy + usx);                   // Z[j]
                   zm = make_float2(udx + usy, usx - udy); }                 // Z[m-j]
        }
        zbuf[p] = zb; zmbuf[p] = zm;
    }
    Tw7 tw = make_tw7(L);
    __syncthreads();

    const float inv = 1.0f / (float)m;
    #pragma unroll
    for (int r = 0; r < ((M + 7) >> 3); r++) {
        int ss = (M >= 8) ? 0 : (w / M);
        int t2 = (M >= 8) ? ((r << 3) + w) : (w - ss * M);
        float2 v[4];
        if (M == 1) {
            // full 128-point spectrum: G[q] = zbuf[q] (q<=64) else Z[q]=zmbuf[128-q]
            #pragma unroll
            for (int j = 0; j < 4; j++) {
                int q = 32 * j + L;
                float2 G = (q <= 64) ? zbuf[ss * 128 + q] : zmbuf[ss * 128 + (128 - q)];
                v[j] = cconj(G);
            }
        } else {
            float2 cf = cconj(lut4096((t2 * (4096 / M)) & 4095));
            #pragma unroll
            for (int j = 0; j < 4; j++) {
                int q = 32 * j + L;
                float2 t = cadd(cconj(zbuf[ss * 128 + q]),
                                cmul(cf, cconj(zmbuf[ss * 128 + ((128 - q) & 127)])));
                v[j] = cmul(lut4096((q * t2 * R) & 4095), t);
            }
        }
        fft128(v, tw, L);
        float2* ob = obuf + ss * PADM;
        #pragma unroll
        for (int j = 0; j < 4; j++) {
            int p = 32 * j + L;
            int u = (int)(__brev((unsigned)p) >> 25);
            int t = M * u + t2;
            ob[t + (t >> 5)] = make_float2(v[j].x * inv, -v[j].y * inv);   // conj/m
        }
    }
    __syncthreads();

    for (int t = tid; t < SPB * m; t += 256) {
        int ss = t / m, tt = t - ss * m;
        float2 vv = obuf[ss * PADM + tt + (tt >> 5)];
        size_t o = uoff + (size_t)(sbase + ss) * m + tt;
        g_Ud[o] = vv.x;
        g_Us[o] = vv.y;
    }
}

// ---------------- generic small FFT (shared mem, sincosf; m <= 64 only) ------------
__device__ __forceinline__ void fft_sm(float2* sb, int m, int logm, float sgn) {
    int T = blockDim.x;
    for (int st = 1; st <= logm; st++) {
        int half = 1 << (st - 1);
        float scale = sgn * 6.283185307179586f / (float)(1 << st);
        for (int idx = threadIdx.x; idx < (m >> 1); idx += T) {
            int j = idx & (half - 1);
            int pos = ((idx >> (st - 1)) << st) + j;
            float sw, cw;
            sincosf(scale * (float)j, &sw, &cw);
            float2 u = sb[pos], v = sb[pos + half];
            float2 tv = make_float2(v.x * cw - v.y * sw, v.x * sw + v.y * cw);
            sb[pos]        = make_float2(u.x + tv.x, u.y + tv.y);
            sb[pos + half] = make_float2(u.x - tv.x, u.y - tv.y);
        }
        __syncthreads();
    }
}

// ---------------- batched forward FFT for levels 6..12 (m = 64 >> ly) --------------
__global__ void k_fftf_tail() {
    __shared__ float2 sb[64];
    int ly = blockIdx.y;
    int lev = 6 + ly;
    int m = 64 >> ly, logm = 6 - ly;
    int l = c_l[lev];
    int modeoff = c_modeoff[lev];
    int s = blockIdx.x;
    const float2* zin = g_zall + (size_t)c_zoff[lev] * SEQ + (size_t)s * m;
    for (int t = threadIdx.x; t < m; t += 32) {
        int r = logm ? (int)(__brev((unsigned)t) >> (32 - logm)) : 0;
        sb[r] = zin[t];
    }
    __syncthreads();
    fft_sm(sb, m, logm, -1.0f);
    for (int k = threadIdx.x; k < l; k += 32) {
        float2 Zk = sb[k];
        float2 Zm = sb[(m - k) & (m - 1)];
        float2 Df = make_float2(0.5f * (Zk.x + Zm.x), 0.5f * (Zk.y - Zm.y));
        float2 Sf = make_float2(0.5f * (Zk.y + Zm.y), 0.5f * (Zm.x - Zk.x));
        g_Df[(size_t)(modeoff + k) * SEQ + s] = Df;
        g_Sf[(size_t)(modeoff + k) * SEQ + s] = Sf;
    }
}

// ---------------- single-launch mixing over ALL levels -----------------------------
__global__ void __launch_bounds__(128) k_mix_all() {
    __shared__ float2 sdf[16][32], ssf[16][32];
    int blk = blockIdx.x;
    int lev = 0;
    #pragma unroll
    for (int i = 1; i < 13; i++) if (blk >= c_mixblk[i]) lev = i;
    int local = blk - c_mixblk[lev];
    int l = c_l[lev], nch = c_nch[lev];
    int ilen = 128 / nch;
    int ch = local / l, mode = local - ch * l;
    int modeoff = c_modeoff[lev], pudoff = c_pudoff[lev];

    int i0 = ch * ilen;
    int cnt = 16 * ilen;
    for (int idx = threadIdx.x; idx < cnt; idx += 128) {
        int bb = idx / ilen, ii = idx - bb * ilen;
        size_t src = (size_t)(modeoff + mode) * SEQ + bb * 128 + i0 + ii;
        sdf[bb][ii] = g_Df[src];
        ssf[bb][ii] = g_Sf[src];
    }
    __syncthreads();
    int o = threadIdx.x;
    float udr[16], udi[16], usr[16], usi[16];
    #pragma unroll
    for (int b = 0; b < 16; b++) { udr[b] = udi[b] = usr[b] = usi[b] = 0.f; }
    for (int ii = 0; ii < ilen; ii++) {
        size_t widx = ((size_t)mode * 128 + (i0 + ii)) * 128 + o;
        float ar = g_wt[widx],          ai = g_wt[W3 + widx];
        float br = g_wt[2 * W3 + widx], bi = g_wt[3 * W3 + widx];
        float cr = g_wt[4 * W3 + widx], ci = g_wt[5 * W3 + widx];
        #pragma unroll
        for (int b = 0; b < 16; b++) {
            float2 df = sdf[b][ii], sf = ssf[b][ii];
            udr[b] += df.x * ar - df.y * ai + sf.x * br - sf.y * bi;
            udi[b] += df.x * ai + df.y * ar + sf.x * bi + sf.y * br;
            usr[b] += df.x * cr - df.y * ci;
            usi[b] += df.x * ci + df.y * cr;
        }
    }
    size_t base = (size_t)(pudoff + ch * l + mode) * SEQ + o;
    #pragma unroll
    for (int b = 0; b < 16; b++) {
        g_pud[base + b * 128] = make_float2(udr[b], udi[b]);
        g_pus[base + b * 128] = make_float2(usr[b], usi[b]);
    }
}

// ---------------- batched inverse FFT for levels 6..12 -----------------------------
__global__ void k_ffti_tail() {
    __shared__ float2 sb[64];
    int ly = blockIdx.y;
    int lev = 6 + ly;
    int m = 64 >> ly, logm = 6 - ly;
    int l = c_l[lev], nch = c_nch[lev], pudoff = c_pudoff[lev];
    int s = blockIdx.x;
    for (int k = threadIdx.x; k < m; k += 32) {
        float2 Z = make_float2(0.f, 0.f);
        int j = -1, cj = 0;
        if (k < l) { j = k; }
        else { int jm = m - k; if (jm < l) { j = jm; cj = 1; } }
        if (j >= 0) {
            float udx = 0.f, udy = 0.f, usx = 0.f, usy = 0.f;
            for (int ch = 0; ch < nch; ch++) {
                size_t base = (size_t)(pudoff + ch * l + j) * SEQ + s;
                float2 a = g_pud[base]; udx += a.x; udy += a.y;
                float2 c = g_pus[base]; usx += c.x; usy += c.y;
            }
            if (!cj) {
                if (j == 0 || 2 * j == m) Z = make_float2(udx, usx);
                else                      Z = make_float2(udx - usy, udy + usx);
            } else {
                Z = make_float2(udx + usy, usx - udy);
            }
        }
        int r = logm ? (int)(__brev((unsigned)k) >> (32 - logm)) : 0;
        sb[r] = Z;
    }
    __syncthreads();
    fft_sm(sb, m, logm, +1.0f);
    float inv = 1.0f / (float)m;
    float* pud = g_Ud + (size_t)c_zoff[lev] * SEQ + (size_t)s * m;
    float* pus = g_Us + (size_t)c_zoff[lev] * SEQ + (size_t)s * m;
    for (int t = threadIdx.x; t < m; t += 32) {
        float2 v = sb[t];
        pud[t] = v.x * inv;
        pus[t] = v.y * inv;
    }
}

// ---------------- coarsest-scale T0 linear map ----------------
__global__ void k_t0(const float* __restrict__ xin, const float* __restrict__ w,
                     const float* __restrict__ bias, float* __restrict__ out) {
    int id = blockIdx.x * blockDim.x + threadIdx.x;
    if (id >= 512) return;
    float v[4];
    #pragma unroll
    for (int k = 0; k < 4; k++) v[k] = xin[id * 4 + k];
    #pragma unroll
    for (int kp = 0; kp < 4; kp++) {
        float a = __ldg(&bias[kp]);
        #pragma unroll
        for (int k = 0; k < 4; k++) a += v[k] * __ldg(&w[kp * 4 + k]);
        out[id * 4 + kp] = a;
    }
}

// ---------------- reconstruction ----------------
__global__ void k_rec(const float* __restrict__ rin, int m, size_t off,
                      float* __restrict__ rout, int final_,
                      const float* __restrict__ rce, const float* __restrict__ rco) {
    int id = blockIdx.x * blockDim.x + threadIdx.x;
    if (id >= 512 * m) return;
    int t = id % m;
    int bc = id / m;
    int row0 = bc * 4;
    float xs[4], ud[4];
    #pragma unroll
    for (int k = 0; k < 4; k++) {
        size_t o = (size_t)(row0 + k) * m + t;
        xs[k] = rin[o] + g_Us[off + o];
        ud[k] = g_Ud[off + o];
    }
    float ev[4], ov[4];
    #pragma unroll
    for (int kp = 0; kp < 4; kp++) {
        float e = 0.f, o = 0.f;
        #pragma unroll
        for (int j = 0; j < 4; j++) {
            e += xs[j] * __ldg(&rce[j * 4 + kp]) + ud[j] * __ldg(&rce[(4 + j) * 4 + kp]);
            o += xs[j] * __ldg(&rco[j * 4 + kp]) + ud[j] * __ldg(&rco[(4 + j) * 4 + kp]);
        }
        ev[kp] = e; ov[kp] = o;
    }
    if (final_) {
        int b = bc >> 5, c = bc & 31;
        float* p0 = rout + (((size_t)b * NSEQ + 2 * t) * 32 + c) * 4;
        float* p1 = p0 + 128;
        #pragma unroll
        for (int kp = 0; kp < 4; kp++) { p0[kp] = ev[kp]; p1[kp] = ov[kp]; }
    } else {
        #pragma unroll
        for (int kp = 0; kp < 4; kp++) {
            size_t o = (size_t)(row0 + kp) * (2 * m);
            rout[o + 2 * t]     = ev[kp];
            rout[o + 2 * t + 1] = ov[kp];
        }
    }
}

// ---------------- host orchestration ----------------
extern "C" void kernel_launch(void* const* d_in, const int* in_sizes, int n_in,
                              void* d_out, int out_size) {
    const float* x   = (const float*)d_in[0];
    const float* wAr = (const float*)d_in[1];
    const float* wAi = (const float*)d_in[2];
    const float* wBr = (const float*)d_in[3];
    const float* wBi = (const float*)d_in[4];
    const float* wCr = (const float*)d_in[5];
    const float* wCi = (const float*)d_in[6];
    const float* ecs = (const float*)d_in[7];
    const float* ecd = (const float*)d_in[8];
    const float* rce = (const float*)d_in[9];
    const float* rco = (const float*)d_in[10];
    const float* t0w = (const float*)d_in[11];
    const float* t0b = (const float*)d_in[12];
    float* out = (float*)d_out;

    float *p_xt, *p_x0, *p_x1; float2 *p_z, *p_zall;
    cudaGetSymbolAddress((void**)&p_xt,   g_xt);
    cudaGetSymbolAddress((void**)&p_x0,   g_x0);
    cudaGetSymbolAddress((void**)&p_x1,   g_x1);
    cudaGetSymbolAddress((void**)&p_z,    g_z);
    cudaGetSymbolAddress((void**)&p_zall, g_zall);

    cudaFuncSetAttribute(k_pfwd<32,1>, cudaFuncAttributeMaxDynamicSharedMemorySize, 70000);

    k_tw<<<8, 256>>>();
    k_tin<<<16 * 256, 256>>>(x);
    k_wt<<<dim3(16, 128, 6), dim3(32, 8)>>>(wAr, wAi, wBr, wBi, wCr, wCi);

    // ---- phase 1: decomposition chain (writes z for every level) ----
    for (int lev = 0; lev < 13; lev++) {
        int m = (NSEQ >> lev) >> 1;
        const float* xin = (lev == 0) ? p_xt : ((lev & 1) ? p_x0 : p_x1);
        float* xnext = (lev & 1) ? p_x1 : p_x0;
        float2* zdst = p_zall + (size_t)h_zoff[lev] * SEQ;
        int tot = 512 * m;
        k_dec<<<(tot + 255) / 256, 256>>>(xin, m, xnext, zdst, ecs, ecd);
    }

    // ---- phase 2: forward FFTs, all levels ----
    {
        auto smF = [](int m, int spb) { return (size_t)(spb * (m + m / 32) + spb * m) * sizeof(float2); };
        k_pfwd<32,1><<<SEQ,     256, smF(4096,1)>>>(p_zall + (size_t)h_zoff[0]*SEQ, h_modeoff[0], h_l[0]);
        k_pfwd<16,1><<<SEQ,     256, smF(2048,1)>>>(p_zall + (size_t)h_zoff[1]*SEQ, h_modeoff[1], h_l[1]);
        k_pfwd<8, 1><<<SEQ,     256, smF(1024,1)>>>(p_zall + (size_t)h_zoff[2]*SEQ, h_modeoff[2], h_l[2]);
        k_pfwd<4, 2><<<SEQ / 2, 256, smF(512, 2)>>>(p_zall + (size_t)h_zoff[3]*SEQ, h_modeoff[3], h_l[3]);
        k_pfwd<2, 4><<<SEQ / 4, 256, smF(256, 4)>>>(p_zall + (size_t)h_zoff[4]*SEQ, h_modeoff[4], h_l[4]);
        k_pfwd<1, 8><<<SEQ / 8, 256, smF(128, 8)>>>(p_zall + (size_t)h_zoff[5]*SEQ, h_modeoff[5], h_l[5]);
        k_fftf_tail<<<dim3(SEQ, 7), 32>>>();
    }

    // ---- phase 3: one mixing launch over all levels (weights stay in L2) ----
    k_mix_all<<<3544, 128>>>();

    // ---- phase 4: inverse FFTs, all levels ----
    {
        auto smI = [](int m, int spb) { return (size_t)(spb * 256 + spb * (m + m / 32)) * sizeof(float2); };
        k_pinv<32,1><<<SEQ,     256, smI(4096,1)>>>(h_pudoff[0], h_l[0], h_nch[0], (size_t)h_zoff[0]*SEQ);
        k_pinv<16,1><<<SEQ,     256, smI(2048,1)>>>(h_pudoff[1], h_l[1], h_nch[1], (size_t)h_zoff[1]*SEQ);
        k_pinv<8, 1><<<SEQ,     256, smI(1024,1)>>>(h_pudoff[2], h_l[2], h_nch[2], (size_t)h_zoff[2]*SEQ);
        k_pinv<4, 2><<<SEQ / 2, 256, smI(512, 2)>>>(h_pudoff[3], h_l[3], h_nch[3], (size_t)h_zoff[3]*SEQ);
        k_pinv<2, 4><<<SEQ / 4, 256, smI(256, 4)>>>(h_pudoff[4], h_l[4], h_nch[4], (size_t)h_zoff[4]*SEQ);
        k_pinv<1, 8><<<SEQ / 8, 256, smI(128, 8)>>>(h_pudoff[5], h_l[5], h_nch[5], (size_t)h_zoff[5]*SEQ);
        k_ffti_tail<<<dim3(SEQ, 7), 32>>>();
    }

    // ---- phase 5: T0 + reconstruction chain ----
    k_t0<<<2, 256>>>(p_x0, t0w, t0b, p_xt);

    float* bufA = p_xt;
    float* bufB = (float*)p_z;
    float* cur = bufA;
    for (int lev = 12; lev >= 0; lev--) {
        int m = (NSEQ >> lev) >> 1;
        size_t off = (size_t)h_zoff[lev] * SEQ;
        int fin = (lev == 0);
        float* rout = fin ? out : ((cur == bufA) ? bufB : bufA);
        int tot = 512 * m;
        k_rec<<<(tot + 255) / 256, 256>>>(cur, m, off, rout, fin, rce, rco);
        if (!fin) cur = rout;
    }
    (void)in_sizes; (void)n_in; (void)out_size;
}

// round 10
// speedup vs baseline: 1.8498x; 1.0403x over previous
#include <cuda_runtime.h>

#define SEQ   2048          // B * CK
#define CKD   128
#define NSEQ  8192
#define W3    (128*128*128)

// ---------------- static device scratch (no allocations allowed) ----------------
__device__ float  g_xt[SEQ * NSEQ];       // recon buf A
__device__ float2 g_z  [SEQ * 4096];      // recon buf B
__device__ float2 g_zall[SEQ * 8191];     // packed d + i*s, ALL levels (offsets c_zoff)
__device__ float  g_x0 [SEQ * 4096];      // smooth coeffs ping
__device__ float  g_x1 [SEQ * 2048];      // smooth coeffs pong
__device__ float  g_xfin[SEQ];            // coarsest x (512 bc * 4 k)
__device__ float2 g_Df [775 * SEQ];       // (global mode, s) spectra of d, all levels
__device__ float2 g_Sf [775 * SEQ];       // (global mode, s) spectra of s
__device__ float2 g_pud[3544 * SEQ];      // partial UdF, all levels (offsets c_pudoff)
__device__ float2 g_pus[3544 * SEQ];      // partial UsF
__device__ float  g_wt [6 * W3];          // weights transposed to (w, mode, i, o)
__device__ float  g_Ud [SEQ * 8191];      // detail outputs, all levels
__device__ float  g_Us [SEQ * 8191];      // smooth outputs, all levels
__device__ float2 g_tw [2048];            // tw[x] = exp(-2*pi*i*x/4096)

// ---------------- per-level tables ----------------
__constant__ int c_l[13]       = {128,128,128,128,128,65,33,17,9,5,3,2,1};
__constant__ int c_nch[13]     = {4,4,4,4,4,4,4,16,16,16,16,16,16};
__constant__ int c_modeoff[13] = {0,128,256,384,512,640,705,738,755,764,769,772,774};
__constant__ int c_pudoff[13]  = {0,512,1024,1536,2048,2560,2820,2952,3224,3368,3448,3496,3528};
__constant__ int c_mixblk[14]  = {0,512,1024,1536,2048,2560,2820,2952,3224,3368,3448,3496,3528,3544};
__constant__ int c_zoff[13]    = {0,4096,6144,7168,7680,7936,8064,8128,8160,8176,8184,8188,8190};

static const int h_l[13]       = {128,128,128,128,128,65,33,17,9,5,3,2,1};
static const int h_nch[13]     = {4,4,4,4,4,4,4,16,16,16,16,16,16};
static const int h_modeoff[13] = {0,128,256,384,512,640,705,738,755,764,769,772,774};
static const int h_pudoff[13]  = {0,512,1024,1536,2048,2560,2820,2952,3224,3368,3448,3496,3528};
static const int h_zoff[13]    = {0,4096,6144,7168,7680,7936,8064,8128,8160,8176,8184,8188,8190};

// ---------------- complex helpers ----------------
__device__ __forceinline__ float2 cadd(float2 a, float2 b){ return make_float2(a.x+b.x, a.y+b.y); }
__device__ __forceinline__ float2 csub(float2 a, float2 b){ return make_float2(a.x-b.x, a.y-b.y); }
__device__ __forceinline__ float2 cmul(float2 a, float2 b){
    return make_float2(fmaf(a.x, b.x, -a.y*b.y), fmaf(a.x, b.y, a.y*b.x));
}
__device__ __forceinline__ float2 cconj(float2 a){ return make_float2(a.x, -a.y); }
__device__ __forceinline__ float2 lut4096(int x){
    float2 t = __ldg(&g_tw[x & 2047]);
    if (x & 2048) { t.x = -t.x; t.y = -t.y; }
    return t;
}

// ---------------- twiddle table ----------------
__global__ void k_tw() {
    int x = blockIdx.x * blockDim.x + threadIdx.x;
    if (x >= 2048) return;
    float ang = -6.283185307179586f * (float)x / 4096.0f;
    float s, c;
    sincosf(ang, &s, &c);
    g_tw[x] = make_float2(c, s);
}

// ---------------- weight transpose: (i,o,mode) -> (mode,i,o) ----------------
__global__ void k_wt(const float* __restrict__ wAr, const float* __restrict__ wAi,
                     const float* __restrict__ wBr, const float* __restrict__ wBi,
                     const float* __restrict__ wCr, const float* __restrict__ wCi) {
    __shared__ float tile[32][33];
    int w = blockIdx.z;
    int i = blockIdx.y;
    int ot = (blockIdx.x >> 2) << 5;
    int mt = (blockIdx.x & 3) << 5;
    const float* src;
    switch (w) {
        case 0: src = wAr; break; case 1: src = wAi; break;
        case 2: src = wBr; break; case 3: src = wBi; break;
        case 4: src = wCr; break; default: src = wCi; break;
    }
    int tx = threadIdx.x, ty = threadIdx.y;
    #pragma unroll
    for (int j = 0; j < 32; j += 8)
        tile[ty + j][tx] = src[((size_t)i * 128 + ot + ty + j) * 128 + mt + tx];
    __syncthreads();
    float* dst = g_wt + (size_t)w * W3;
    #pragma unroll
    for (int j = 0; j < 32; j += 8)
        dst[((size_t)(mt + ty + j) * 128 + i) * 128 + ot + tx] = tile[tx][ty + j];
}

// ---------------- level-0 decompose: reads original (B,N,C,K) layout directly ------
__global__ void k_dec0(const float* __restrict__ x,
                       float* __restrict__ xnext, float2* __restrict__ zdst,
                       const float* __restrict__ ecs, const float* __restrict__ ecd) {
    int id = blockIdx.x * blockDim.x + threadIdx.x;
    if (id >= 512 * 4096) return;
    int t = id & 4095;
    int bc = id >> 12;
    int b = bc >> 5, c = bc & 31;
    // x[b, 2t, c, 0..3] and x[b, 2t+1, c, 0..3]: two contiguous float4s
    const float4* pe = (const float4*)(x + (((size_t)b * NSEQ + 2 * t) * 32 + c) * 4);
    const float4* po = (const float4*)(x + (((size_t)b * NSEQ + 2 * t + 1) * 32 + c) * 4);
    float4 e = *pe, o4 = *po;
    float xa[8] = {e.x, e.y, e.z, e.w, o4.x, o4.y, o4.z, o4.w};
    int row0 = bc * 4;
    #pragma unroll
    for (int kp = 0; kp < 4; kp++) {
        float d = 0.f, s = 0.f;
        #pragma unroll
        for (int j = 0; j < 8; j++) {
            d += xa[j] * __ldg(&ecd[j * 4 + kp]);
            s += xa[j] * __ldg(&ecs[j * 4 + kp]);
        }
        size_t o = (size_t)(row0 + kp) * 4096 + t;
        zdst[o] = make_float2(d, s);
        xnext[o] = s;
    }
}

// ---------------- decompose levels 1..6: filter bank + pack z = d + i*s ------------
__global__ void k_dec(const float* __restrict__ xin, int m,
                      float* __restrict__ xnext, float2* __restrict__ zdst,
                      const float* __restrict__ ecs, const float* __restrict__ ecd) {
    int id = blockIdx.x * blockDim.x + threadIdx.x;
    if (id >= 512 * m) return;
    int t = id % m;
    int bc = id / m;
    int row0 = bc * 4;
    int n = 2 * m;
    float xa[8];
    #pragma unroll
    for (int k = 0; k < 4; k++) {
        const float* p = xin + (size_t)(row0 + k) * n + 2 * t;
        xa[k]     = p[0];
        xa[4 + k] = p[1];
    }
    #pragma unroll
    for (int kp = 0; kp < 4; kp++) {
        float d = 0.f, s = 0.f;
        #pragma unroll
        for (int j = 0; j < 8; j++) {
            d += xa[j] * __ldg(&ecd[j * 4 + kp]);
            s += xa[j] * __ldg(&ecs[j * 4 + kp]);
        }
        size_t o = (size_t)(row0 + kp) * m + t;
        zdst[o] = make_float2(d, s);
        xnext[o] = s;
    }
}

// ---------------- batched decompose chain, levels 7..12 ----------------------------
__global__ void __launch_bounds__(32) k_dec_tail(const float* __restrict__ xin,
                                                 const float* __restrict__ ecs,
                                                 const float* __restrict__ ecd) {
    __shared__ float sx[4][64];
    int bc = blockIdx.x;
    int tid = threadIdx.x;
    for (int i = tid; i < 256; i += 32)
        sx[i >> 6][i & 63] = xin[(size_t)(bc * 4 + (i >> 6)) * 64 + (i & 63)];
    __syncthreads();
    int m = 32;
    for (int lev = 7; lev <= 12; lev++) {
        float dv[4], sv[4];
        if (tid < m) {
            float xa[8];
            #pragma unroll
            for (int k = 0; k < 4; k++) {
                xa[k]     = sx[k][2 * tid];
                xa[4 + k] = sx[k][2 * tid + 1];
            }
            #pragma unroll
            for (int kp = 0; kp < 4; kp++) {
                float d = 0.f, s = 0.f;
                #pragma unroll
                for (int j = 0; j < 8; j++) {
                    d += xa[j] * __ldg(&ecd[j * 4 + kp]);
                    s += xa[j] * __ldg(&ecs[j * 4 + kp]);
                }
                dv[kp] = d; sv[kp] = s;
            }
        }
        __syncthreads();
        if (tid < m) {
            float2* z = g_zall + (size_t)c_zoff[lev] * SEQ;
            #pragma unroll
            for (int kp = 0; kp < 4; kp++) {
                z[(size_t)(bc * 4 + kp) * m + tid] = make_float2(dv[kp], sv[kp]);
                sx[kp][tid] = sv[kp];
            }
        }
        __syncthreads();
        m >>= 1;
    }
    if (tid == 0) {
        #pragma unroll
        for (int kp = 0; kp < 4; kp++) g_xfin[bc * 4 + kp] = sx[kp][0];
    }
}

// ================= register-resident warp FFT-128 (DIF, output bit-reversed) ==========
struct Tw7 { float2 wA, wB, w32, w16, w8, w4, w2; };

__device__ __forceinline__ Tw7 make_tw7(int L) {
    Tw7 t;
    t.wA  = __ldg(&g_tw[L * 32]);
    t.wB  = __ldg(&g_tw[(L + 32) * 32]);
    t.w32 = __ldg(&g_tw[L * 64]);
    t.w16 = __ldg(&g_tw[(L & 15) * 128]);
    t.w8  = __ldg(&g_tw[(L & 7) * 256]);
    t.w4  = __ldg(&g_tw[(L & 3) * 512]);
    t.w2  = __ldg(&g_tw[(L & 1) * 1024]);
    return t;
}

__device__ __forceinline__ void cross_stage(float2& x, int bit, float2 w, int L) {
    float ox = __shfl_xor_sync(0xFFFFFFFFu, x.x, bit);
    float oy = __shfl_xor_sync(0xFFFFFFFFu, x.y, bit);
    if (L & bit) x = cmul(make_float2(ox - x.x, oy - x.y), w);
    else         x = make_float2(x.x + ox, x.y + oy);
}
__device__ __forceinline__ void cross_last(float2& x, int L) {
    float ox = __shfl_xor_sync(0xFFFFFFFFu, x.x, 1);
    float oy = __shfl_xor_sync(0xFFFFFFFFu, x.y, 1);
    if (L & 1) x = make_float2(ox - x.x, oy - x.y);
    else       x = make_float2(x.x + ox, x.y + oy);
}

__device__ __forceinline__ void fft128(float2 v[4], const Tw7& tw, int L) {
    float2 a, b;
    a = v[0]; b = v[2]; v[0] = cadd(a, b); v[2] = cmul(csub(a, b), tw.wA);
    a = v[1]; b = v[3]; v[1] = cadd(a, b); v[3] = cmul(csub(a, b), tw.wB);
    a = v[0]; b = v[1]; v[0] = cadd(a, b); v[1] = cmul(csub(a, b), tw.w32);
    a = v[2]; b = v[3]; v[2] = cadd(a, b); v[3] = cmul(csub(a, b), tw.w32);
    #pragma unroll
    for (int j = 0; j < 4; j++) cross_stage(v[j], 16, tw.w16, L);
    #pragma unroll
    for (int j = 0; j < 4; j++) cross_stage(v[j], 8, tw.w8, L);
    #pragma unroll
    for (int j = 0; j < 4; j++) cross_stage(v[j], 4, tw.w4, L);
    #pragma unroll
    for (int j = 0; j < 4; j++) cross_stage(v[j], 2, tw.w2, L);
    #pragma unroll
    for (int j = 0; j < 4; j++) cross_last(v[j], L);
}

// ---------------- pruned forward: m = 128*M, modes k<l (and m-k) --------------------
template<int M, int SPB>
__global__ void __launch_bounds__(256) k_pfwd(const float2* __restrict__ zin0,
                                              int modeoff, int l) {
    constexpr int m = 128 * M;
    constexpr int R = 32 / M;
    constexpr int PADM = m + (m >> 5);
    extern __shared__ float2 sm[];
    float2* xin  = sm;
    float2* ybuf = sm + SPB * PADM;
    int tid = threadIdx.x, L = tid & 31, w = tid >> 5;
    int sbase = blockIdx.x * SPB;

    for (int t = tid; t < SPB * m; t += 256) {
        int ss = t / m, tt = t - ss * m;
        xin[ss * PADM + tt + (tt >> 5)] = zin0[(size_t)(sbase + ss) * m + tt];
    }
    Tw7 tw = make_tw7(L);
    __syncthreads();

    #pragma unroll
    for (int r = 0; r < ((M + 7) >> 3); r++) {
        int ss = (M >= 8) ? 0 : (w / M);
        int t2 = (M >= 8) ? ((r << 3) + w) : (w - ss * M);
        float2 v[4];
        const float2* xb = xin + ss * PADM;
        #pragma unroll
        for (int j = 0; j < 4; j++) {
            int t = M * (32 * j + L) + t2;
            v[j] = xb[t + (t >> 5)];
        }
        fft128(v, tw, L);
        #pragma unroll
        for (int j = 0; j < 4; j++) {
            int p = 32 * j + L;
            int q = (int)(__brev((unsigned)p) >> 25);
            ybuf[ss * m + t2 * 128 + q] = v[j];
        }
    }
    __syncthreads();

    for (int p = tid; p < SPB * 128; p += 256) {
        int ss = p >> 7, k = p & 127;
        if (k >= l) continue;
        int k2 = (128 - k) & 127;
        const float2* yb = ybuf + ss * m;
        float2 Xk = make_float2(0.f, 0.f), Xm = make_float2(0.f, 0.f);
        int step = (k * R) & 4095;
        int idx = 0;
        for (int t2 = 0; t2 < M; t2++) {
            float2 wtw = lut4096(idx);
            Xk = cadd(Xk, cmul(wtw, yb[t2 * 128 + k]));
            Xm = cadd(Xm, cmul(cconj(wtw), yb[t2 * 128 + k2]));
            idx = (idx + step) & 4095;
        }
        int s = sbase + ss;
        float2 Df = make_float2(0.5f * (Xk.x + Xm.x), 0.5f * (Xk.y - Xm.y));
        float2 Sf = make_float2(0.5f * (Xk.y + Xm.y), 0.5f * (Xm.x - Xk.x));
        g_Df[(size_t)(modeoff + k) * SEQ + s] = Df;
        g_Sf[(size_t)(modeoff + k) * SEQ + s] = Sf;
    }
}

// ---------------- pruned inverse --------------------------------------------------
template<int M, int SPB>
__global__ void __launch_bounds__(256) k_pinv(int pudoff, int l, int nch, size_t uoff) {
    constexpr int m = 128 * M;
    constexpr int R = 32 / M;
    constexpr int PADM = m + (m >> 5);
    extern __shared__ float2 sm[];
    float2* zbuf  = sm;
    float2* zmbuf = sm + SPB * 128;
    float2* obuf  = sm + SPB * 256;
    int tid = threadIdx.x, L = tid & 31, w = tid >> 5;
    int sbase = blockIdx.x * SPB;

    for (int p = tid; p < SPB * 128; p += 256) {
        int ss = p >> 7, j = p & 127;
        int s = sbase + ss;
        float2 zb = make_float2(0.f, 0.f), zm = make_float2(0.f, 0.f);
        if (j < l) {
            float udx = 0.f, udy = 0.f, usx = 0.f, usy = 0.f;
            for (int ch = 0; ch < nch; ch++) {
                size_t base = (size_t)(pudoff + ch * l + j) * SEQ + s;
                float2 a = g_pud[base]; udx += a.x; udy += a.y;
                float2 c = g_pus[base]; usx += c.x; usy += c.y;
            }
            if (j == 0 || 2 * j == m) { zb = make_float2(udx, usx); }
            else { zb = make_float2(udx - usy, udy + usx);
                   zm = make_float2(udx + usy, usx - udy); }
        }
        zbuf[p] = zb; zmbuf[p] = zm;
    }
    Tw7 tw = make_tw7(L);
    __syncthreads();

    const float inv = 1.0f / (float)m;
    #pragma unroll
    for (int r = 0; r < ((M + 7) >> 3); r++) {
        int ss = (M >= 8) ? 0 : (w / M);
        int t2 = (M >= 8) ? ((r << 3) + w) : (w - ss * M);
        float2 v[4];
        if (M == 1) {
            #pragma unroll
            for (int j = 0; j < 4; j++) {
                int q = 32 * j + L;
                float2 G = (q <= 64) ? zbuf[ss * 128 + q] : zmbuf[ss * 128 + (128 - q)];
                v[j] = cconj(G);
            }
        } else {
            float2 cf = cconj(lut4096((t2 * (4096 / M)) & 4095));
            #pragma unroll
            for (int j = 0; j < 4; j++) {
                int q = 32 * j + L;
                float2 t = cadd(cconj(zbuf[ss * 128 + q]),
                                cmul(cf, cconj(zmbuf[ss * 128 + ((128 - q) & 127)])));
                v[j] = cmul(lut4096((q * t2 * R) & 4095), t);
            }
        }
        fft128(v, tw, L);
        float2* ob = obuf + ss * PADM;
        #pragma unroll
        for (int j = 0; j < 4; j++) {
            int p = 32 * j + L;
            int u = (int)(__brev((unsigned)p) >> 25);
            int t = M * u + t2;
            ob[t + (t >> 5)] = make_float2(v[j].x * inv, -v[j].y * inv);
        }
    }
    __syncthreads();

    for (int t = tid; t < SPB * m; t += 256) {
        int ss = t / m, tt = t - ss * m;
        float2 vv = obuf[ss * PADM + tt + (tt >> 5)];
        size_t o = uoff + (size_t)(sbase + ss) * m + tt;
        g_Ud[o] = vv.x;
        g_Us[o] = vv.y;
    }
}

// ---------------- generic small FFT (shared mem, sincosf; m <= 64 only) ------------
__device__ __forceinline__ void fft_sm(float2* sb, int m, int logm, float sgn) {
    int T = blockDim.x;
    for (int st = 1; st <= logm; st++) {
        int half = 1 << (st - 1);
        float scale = sgn * 6.283185307179586f / (float)(1 << st);
        for (int idx = threadIdx.x; idx < (m >> 1); idx += T) {
            int j = idx & (half - 1);
            int pos = ((idx >> (st - 1)) << st) + j;
            float sw, cw;
            sincosf(scale * (float)j, &sw, &cw);
            float2 u = sb[pos], v = sb[pos + half];
            float2 tv = make_float2(v.x * cw - v.y * sw, v.x * sw + v.y * cw);
            sb[pos]        = make_float2(u.x + tv.x, u.y + tv.y);
            sb[pos + half] = make_float2(u.x - tv.x, u.y - tv.y);
        }
        __syncthreads();
    }
}

// ---------------- batched forward FFT for levels 6..12 -----------------------------
__global__ void k_fftf_tail() {
    __shared__ float2 sb[64];
    int ly = blockIdx.y;
    int lev = 6 + ly;
    int m = 64 >> ly, logm = 6 - ly;
    int l = c_l[lev];
    int modeoff = c_modeoff[lev];
    int s = blockIdx.x;
    const float2* zin = g_zall + (size_t)c_zoff[lev] * SEQ + (size_t)s * m;
    for (int t = threadIdx.x; t < m; t += 32) {
        int r = logm ? (int)(__brev((unsigned)t) >> (32 - logm)) : 0;
        sb[r] = zin[t];
    }
    __syncthreads();
    fft_sm(sb, m, logm, -1.0f);
    for (int k = threadIdx.x; k < l; k += 32) {
        float2 Zk = sb[k];
        float2 Zm = sb[(m - k) & (m - 1)];
        float2 Df = make_float2(0.5f * (Zk.x + Zm.x), 0.5f * (Zk.y - Zm.y));
        float2 Sf = make_float2(0.5f * (Zk.y + Zm.y), 0.5f * (Zm.x - Zk.x));
        g_Df[(size_t)(modeoff + k) * SEQ + s] = Df;
        g_Sf[(size_t)(modeoff + k) * SEQ + s] = Sf;
    }
}

// ---------------- single-launch mixing over ALL levels -----------------------------
__global__ void __launch_bounds__(128) k_mix_all() {
    __shared__ float2 sdf[16][32], ssf[16][32];
    int blk = blockIdx.x;
    int lev = 0;
    #pragma unroll
    for (int i = 1; i < 13; i++) if (blk >= c_mixblk[i]) lev = i;
    int local = blk - c_mixblk[lev];
    int l = c_l[lev], nch = c_nch[lev];
    int ilen = 128 / nch;
    int ch = local / l, mode = local - ch * l;
    int modeoff = c_modeoff[lev], pudoff = c_pudoff[lev];

    int i0 = ch * ilen;
    int cnt = 16 * ilen;
    for (int idx = threadIdx.x; idx < cnt; idx += 128) {
        int bb = idx / ilen, ii = idx - bb * ilen;
        size_t src = (size_t)(modeoff + mode) * SEQ + bb * 128 + i0 + ii;
        sdf[bb][ii] = g_Df[src];
        ssf[bb][ii] = g_Sf[src];
    }
    __syncthreads();
    int o = threadIdx.x;
    float udr[16], udi[16], usr[16], usi[16];
    #pragma unroll
    for (int b = 0; b < 16; b++) { udr[b] = udi[b] = usr[b] = usi[b] = 0.f; }
    for (int ii = 0; ii < ilen; ii++) {
        size_t widx = ((size_t)mode * 128 + (i0 + ii)) * 128 + o;
        float ar = g_wt[widx],          ai = g_wt[W3 + widx];
        float br = g_wt[2 * W3 + widx], bi = g_wt[3 * W3 + widx];
        float cr = g_wt[4 * W3 + widx], ci = g_wt[5 * W3 + widx];
        #pragma unroll
        for (int b = 0; b < 16; b++) {
            float2 df = sdf[b][ii], sf = ssf[b][ii];
            udr[b] += df.x * ar - df.y * ai + sf.x * br - sf.y * bi;
            udi[b] += df.x * ai + df.y * ar + sf.x * bi + sf.y * br;
            usr[b] += df.x * cr - df.y * ci;
            usi[b] += df.x * ci + df.y * cr;
        }
    }
    size_t base = (size_t)(pudoff + ch * l + mode) * SEQ + o;
    #pragma unroll
    for (int b = 0; b < 16; b++) {
        g_pud[base + b * 128] = make_float2(udr[b], udi[b]);
        g_pus[base + b * 128] = make_float2(usr[b], usi[b]);
    }
}

// ---------------- batched inverse FFT for levels 6..12 -----------------------------
__global__ void k_ffti_tail() {
    __shared__ float2 sb[64];
    int ly = blockIdx.y;
    int lev = 6 + ly;
    int m = 64 >> ly, logm = 6 - ly;
    int l = c_l[lev], nch = c_nch[lev], pudoff = c_pudoff[lev];
    int s = blockIdx.x;
    for (int k = threadIdx.x; k < m; k += 32) {
        float2 Z = make_float2(0.f, 0.f);
        int j = -1, cj = 0;
        if (k < l) { j = k; }
        else { int jm = m - k; if (jm < l) { j = jm; cj = 1; } }
        if (j >= 0) {
            float udx = 0.f, udy = 0.f, usx = 0.f, usy = 0.f;
            for (int ch = 0; ch < nch; ch++) {
                size_t base = (size_t)(pudoff + ch * l + j) * SEQ + s;
                float2 a = g_pud[base]; udx += a.x; udy += a.y;
                float2 c = g_pus[base]; usx += c.x; usy += c.y;
            }
            if (!cj) {
                if (j == 0 || 2 * j == m) Z = make_float2(udx, usx);
                else                      Z = make_float2(udx - usy, udy + usx);
            } else {
                Z = make_float2(udx + usy, usx - udy);
            }
        }
        int r = logm ? (int)(__brev((unsigned)k) >> (32 - logm)) : 0;
        sb[r] = Z;
    }
    __syncthreads();
    fft_sm(sb, m, logm, +1.0f);
    float inv = 1.0f / (float)m;
    float* pud = g_Ud + (size_t)c_zoff[lev] * SEQ + (size_t)s * m;
    float* pus = g_Us + (size_t)c_zoff[lev] * SEQ + (size_t)s * m;
    for (int t = threadIdx.x; t < m; t += 32) {
        float2 v = sb[t];
        pud[t] = v.x * inv;
        pus[t] = v.y * inv;
    }
}

// ---------------- batched T0 + reconstruction chain, levels 12..7 ------------------
__global__ void __launch_bounds__(32) k_rec_tail(const float* __restrict__ t0w,
                                                 const float* __restrict__ t0b,
                                                 const float* __restrict__ rce,
                                                 const float* __restrict__ rco,
                                                 float* __restrict__ xout) {
    __shared__ float sx[4][64];
    int bc = blockIdx.x;
    int tid = threadIdx.x;
    if (tid == 0) {
        float v[4];
        #pragma unroll
        for (int k = 0; k < 4; k++) v[k] = g_xfin[bc * 4 + k];
        #pragma unroll
        for (int kp = 0; kp < 4; kp++) {
            float a = __ldg(&t0b[kp]);
            #pragma unroll
            for (int k = 0; k < 4; k++) a += v[k] * __ldg(&t0w[kp * 4 + k]);
            sx[kp][0] = a;
        }
    }
    __syncthreads();
    int m = 1;
    for (int lev = 12; lev >= 7; lev--) {
        float ev[4], ov[4];
        if (tid < m) {
            float xs[4], ud[4];
            size_t off = (size_t)c_zoff[lev] * SEQ;
            #pragma unroll
            for (int k = 0; k < 4; k++) {
                size_t o = off + (size_t)(bc * 4 + k) * m + tid;
                xs[k] = sx[k][tid] + g_Us[o];
                ud[k] = g_Ud[o];
            }
            #pragma unroll
            for (int kp = 0; kp < 4; kp++) {
                float e = 0.f, o = 0.f;
                #pragma unroll
                for (int j = 0; j < 4; j++) {
                    e += xs[j] * __ldg(&rce[j * 4 + kp]) + ud[j] * __ldg(&rce[(4 + j) * 4 + kp]);
                    o += xs[j] * __ldg(&rco[j * 4 + kp]) + ud[j] * __ldg(&rco[(4 + j) * 4 + kp]);
                }
                ev[kp] = e; ov[kp] = o;
            }
        }
        __syncthreads();
        if (tid < m) {
            #pragma unroll
            for (int kp = 0; kp < 4; kp++) {
                sx[kp][2 * tid]     = ev[kp];
                sx[kp][2 * tid + 1] = ov[kp];
            }
        }
        __syncthreads();
        m <<= 1;
    }
    for (int i = tid; i < 256; i += 32)
        xout[(size_t)(bc * 4 + (i >> 6)) * 64 + (i & 63)] = sx[i >> 6][i & 63];
}

// ---------------- reconstruction levels 6..0 ----------------
__global__ void k_rec(const float* __restrict__ rin, int m, size_t off,
                      float* __restrict__ rout, int final_,
                      const float* __restrict__ rce, const float* __restrict__ rco) {
    int id = blockIdx.x * blockDim.x + threadIdx.x;
    if (id >= 512 * m) return;
    int t = id % m;
    int bc = id / m;
    int row0 = bc * 4;
    float xs[4], ud[4];
    #pragma unroll
    for (int k = 0; k < 4; k++) {
        size_t o = (size_t)(row0 + k) * m + t;
        xs[k] = rin[o] + g_Us[off + o];
        ud[k] = g_Ud[off + o];
    }
    float ev[4], ov[4];
    #pragma unroll
    for (int kp = 0; kp < 4; kp++) {
        float e = 0.f, o = 0.f;
        #pragma unroll
        for (int j = 0; j < 4; j++) {
            e += xs[j] * __ldg(&rce[j * 4 + kp]) + ud[j] * __ldg(&rce[(4 + j) * 4 + kp]);
            o += xs[j] * __ldg(&rco[j * 4 + kp]) + ud[j] * __ldg(&rco[(4 + j) * 4 + kp]);
        }
        ev[kp] = e; ov[kp] = o;
    }
    if (final_) {
        int b = bc >> 5, c = bc & 31;
        float* p0 = rout + (((size_t)b * NSEQ + 2 * t) * 32 + c) * 4;
        float* p1 = p0 + 128;
        #pragma unroll
        for (int kp = 0; kp < 4; kp++) { p0[kp] = ev[kp]; p1[kp] = ov[kp]; }
    } else {
        #pragma unroll
        for (int kp = 0; kp < 4; kp++) {
            size_t o = (size_t)(row0 + kp) * (2 * m);
            rout[o + 2 * t]     = ev[kp];
            rout[o + 2 * t + 1] = ov[kp];
        }
    }
}

// ---------------- host orchestration ----------------
extern "C" void kernel_launch(void* const* d_in, const int* in_sizes, int n_in,
                              void* d_out, int out_size) {
    const float* x   = (const float*)d_in[0];
    const float* wAr = (const float*)d_in[1];
    const float* wAi = (const float*)d_in[2];
    const float* wBr = (const float*)d_in[3];
    const float* wBi = (const float*)d_in[4];
    const float* wCr = (const float*)d_in[5];
    const float* wCi = (const float*)d_in[6];
    const float* ecs = (const float*)d_in[7];
    const float* ecd = (const float*)d_in[8];
    const float* rce = (const float*)d_in[9];
    const float* rco = (const float*)d_in[10];
    const float* t0w = (const float*)d_in[11];
    const float* t0b = (const float*)d_in[12];
    float* out = (float*)d_out;

    float *p_xt, *p_x0, *p_x1; float2 *p_z, *p_zall;
    cudaGetSymbolAddress((void**)&p_xt,   g_xt);
    cudaGetSymbolAddress((void**)&p_x0,   g_x0);
    cudaGetSymbolAddress((void**)&p_x1,   g_x1);
    cudaGetSymbolAddress((void**)&p_z,    g_z);
    cudaGetSymbolAddress((void**)&p_zall, g_zall);

    cudaFuncSetAttribute(k_pfwd<32,1>, cudaFuncAttributeMaxDynamicSharedMemorySize, 70000);

    k_tw<<<8, 256>>>();
    k_wt<<<dim3(16, 128, 6), dim3(32, 8)>>>(wAr, wAi, wBr, wBi, wCr, wCi);

    // ---- phase 1: decomposition chain ----
    // level 0 reads the original (B,N,C,K) layout directly
    k_dec0<<<(512 * 4096 + 255) / 256, 256>>>(x, p_x0, p_zall + (size_t)h_zoff[0] * SEQ, ecs, ecd);
    for (int lev = 1; lev <= 6; lev++) {
        int m = (NSEQ >> lev) >> 1;
        const float* xin = (lev & 1) ? p_x0 : p_x1;
        float* xnext = (lev & 1) ? p_x1 : p_x0;
        float2* zdst = p_zall + (size_t)h_zoff[lev] * SEQ;
        int tot = 512 * m;
        k_dec<<<(tot + 255) / 256, 256>>>(xin, m, xnext, zdst, ecs, ecd);
    }
    // levels 7..12 chained in one kernel (input: x after level 6, in p_x0)
    k_dec_tail<<<512, 32>>>(p_x0, ecs, ecd);

    // ---- phase 2: forward FFTs, all levels ----
    {
        auto smF = [](int m, int spb) { return (size_t)(spb * (m + m / 32) + spb * m) * sizeof(float2); };
        k_pfwd<32,1><<<SEQ,     256, smF(4096,1)>>>(p_zall + (size_t)h_zoff[0]*SEQ, h_modeoff[0], h_l[0]);
        k_pfwd<16,1><<<SEQ,     256, smF(2048,1)>>>(p_zall + (size_t)h_zoff[1]*SEQ, h_modeoff[1], h_l[1]);
        k_pfwd<8, 1><<<SEQ,     256, smF(1024,1)>>>(p_zall + (size_t)h_zoff[2]*SEQ, h_modeoff[2], h_l[2]);
        k_pfwd<4, 2><<<SEQ / 2, 256, smF(512, 2)>>>(p_zall + (size_t)h_zoff[3]*SEQ, h_modeoff[3], h_l[3]);
        k_pfwd<2, 4><<<SEQ / 4, 256, smF(256, 4)>>>(p_zall + (size_t)h_zoff[4]*SEQ, h_modeoff[4], h_l[4]);
        k_pfwd<1, 8><<<SEQ / 8, 256, smF(128, 8)>>>(p_zall + (size_t)h_zoff[5]*SEQ, h_modeoff[5], h_l[5]);
        k_fftf_tail<<<dim3(SEQ, 7), 32>>>();
    }

    // ---- phase 3: one mixing launch over all levels ----
    k_mix_all<<<3544, 128>>>();

    // ---- phase 4: inverse FFTs, all levels ----
    {
        auto smI = [](int m, int spb) { return (size_t)(spb * 256 + spb * (m + m / 32)) * sizeof(float2); };
        k_pinv<32,1><<<SEQ,     256, smI(4096,1)>>>(h_pudoff[0], h_l[0], h_nch[0], (size_t)h_zoff[0]*SEQ);
        k_pinv<16,1><<<SEQ,     256, smI(2048,1)>>>(h_pudoff[1], h_l[1], h_nch[1], (size_t)h_zoff[1]*SEQ);
        k_pinv<8, 1><<<SEQ,     256, smI(1024,1)>>>(h_pudoff[2], h_l[2], h_nch[2], (size_t)h_zoff[2]*SEQ);
        k_pinv<4, 2><<<SEQ / 2, 256, smI(512, 2)>>>(h_pudoff[3], h_l[3], h_nch[3], (size_t)h_zoff[3]*SEQ);
        k_pinv<2, 4><<<SEQ / 4, 256, smI(256, 4)>>>(h_pudoff[4], h_l[4], h_nch[4], (size_t)h_zoff[4]*SEQ);
        k_pinv<1, 8><<<SEQ / 8, 256, smI(128, 8)>>>(h_pudoff[5], h_l[5], h_nch[5], (size_t)h_zoff[5]*SEQ);
        k_ffti_tail<<<dim3(SEQ, 7), 32>>>();
    }

    // ---- phase 5: T0 + rec levels 12..7 in one kernel, then rec 6..0 ----
    k_rec_tail<<<512, 32>>>(t0w, t0b, rce, rco, p_xt);

    float* bufA = p_xt;
    float* bufB = (float*)p_z;
    float* cur = bufA;
    for (int lev = 6; lev >= 0; lev--) {
        int m = (NSEQ >> lev) >> 1;
        size_t off = (size_t)h_zoff[lev] * SEQ;
        int fin = (lev == 0);
        float* rout = fin ? out : ((cur == bufA) ? bufB : bufA);
        int tot = 512 * m;
        k_rec<<<(tot + 255) / 256, 256>>>(cur, m, off, rout, fin, rce, rco);
        if (!fin) cur = rout;
    }
    (void)in_sizes; (void)n_in; (void)out_size;
}

// round 12
// speedup vs baseline: 2.0685x; 1.1182x over previous
#include <cuda_runtime.h>

#define SEQ   2048          // B * CK
#define CKD   128
#define NSEQ  8192
#define W3    (128*128*128)

typedef unsigned long long ull;

// ---------------- static device scratch (no allocations allowed) ----------------
__device__ float  g_xt[SEQ * NSEQ];       // recon buf A
__device__ float2 g_z  [SEQ * 4096];      // recon buf B
__device__ float2 g_zall[SEQ * 8191];     // packed d + i*s, ALL levels (offsets c_zoff)
__device__ float  g_x0 [SEQ * 4096];      // smooth coeffs ping
__device__ float  g_x1 [SEQ * 2048];      // smooth coeffs pong
__device__ float  g_xfin[SEQ];            // coarsest x (512 bc * 4 k)
__device__ float2 g_Df [775 * SEQ];       // (global mode, s) spectra of d, all levels
__device__ float2 g_Sf [775 * SEQ];       // (global mode, s) spectra of s
__device__ float2 g_pud[775 * SEQ];       // UdF, all levels (offsets c_modeoff)
__device__ float2 g_pus[775 * SEQ];       // UsF
__device__ float  g_wt [6 * W3];          // weights transposed to (w, mode, i, o)
__device__ float  g_Ud [SEQ * 8191];      // detail outputs, all levels
__device__ float  g_Us [SEQ * 8191];      // smooth outputs, all levels
__device__ float2 g_tw [2048];            // tw[x] = exp(-2*pi*i*x/4096)

// ---------------- per-level tables ----------------
__constant__ int c_l[13]       = {128,128,128,128,128,65,33,17,9,5,3,2,1};
__constant__ int c_modeoff[13] = {0,128,256,384,512,640,705,738,755,764,769,772,774};
__constant__ int c_mixblk[14]  = {0,128,256,384,512,640,705,738,755,764,769,772,774,775};
__constant__ int c_zoff[13]    = {0,4096,6144,7168,7680,7936,8064,8128,8160,8176,8184,8188,8190};

static const int h_l[13]       = {128,128,128,128,128,65,33,17,9,5,3,2,1};
static const int h_modeoff[13] = {0,128,256,384,512,640,705,738,755,764,769,772,774};
static const int h_zoff[13]    = {0,4096,6144,7168,7680,7936,8064,8128,8160,8176,8184,8188,8190};

// ---------------- complex / packed helpers ----------------
__device__ __forceinline__ float2 cadd(float2 a, float2 b){ return make_float2(a.x+b.x, a.y+b.y); }
__device__ __forceinline__ float2 csub(float2 a, float2 b){ return make_float2(a.x-b.x, a.y-b.y); }
__device__ __forceinline__ float2 cmul(float2 a, float2 b){
    return make_float2(fmaf(a.x, b.x, -a.y*b.y), fmaf(a.x, b.y, a.y*b.x));
}
__device__ __forceinline__ float2 cconj(float2 a){ return make_float2(a.x, -a.y); }
__device__ __forceinline__ float2 lut4096(int x){
    float2 t = __ldg(&g_tw[x & 2047]);
    if (x & 2048) { t.x = -t.x; t.y = -t.y; }
    return t;
}
__device__ __forceinline__ ull fma2(ull a, ull b, ull c){
    ull d;
    asm("fma.rn.f32x2 %0, %1, %2, %3;" : "=l"(d) : "l"(a), "l"(b), "l"(c));
    return d;
}
__device__ __forceinline__ ull bcast2(float w){
    ull d;
    asm("mov.b64 %0, {%1, %1};" : "=l"(d) : "f"(w));
    return d;
}
__device__ __forceinline__ float lo32(ull v){ return __uint_as_float((unsigned)(v & 0xffffffffull)); }
__device__ __forceinline__ float hi32(ull v){ return __uint_as_float((unsigned)(v >> 32)); }

// ---------------- twiddle table ----------------
__global__ void k_tw() {
    int x = blockIdx.x * blockDim.x + threadIdx.x;
    if (x >= 2048) return;
    float ang = -6.283185307179586f * (float)x / 4096.0f;
    float s, c;
    sincosf(ang, &s, &c);
    g_tw[x] = make_float2(c, s);
}

// ---------------- weight transpose: (i,o,mode) -> (mode,i,o) ----------------
__global__ void k_wt(const float* __restrict__ wAr, const float* __restrict__ wAi,
                     const float* __restrict__ wBr, const float* __restrict__ wBi,
                     const float* __restrict__ wCr, const float* __restrict__ wCi) {
    __shared__ float tile[32][33];
    int w = blockIdx.z;
    int i = blockIdx.y;
    int ot = (blockIdx.x >> 2) << 5;
    int mt = (blockIdx.x & 3) << 5;
    const float* src;
    switch (w) {
        case 0: src = wAr; break; case 1: src = wAi; break;
        case 2: src = wBr; break; case 3: src = wBi; break;
        case 4: src = wCr; break; default: src = wCi; break;
    }
    int tx = threadIdx.x, ty = threadIdx.y;
    #pragma unroll
    for (int j = 0; j < 32; j += 8)
        tile[ty + j][tx] = src[((size_t)i * 128 + ot + ty + j) * 128 + mt + tx];
    __syncthreads();
    float* dst = g_wt + (size_t)w * W3;
    #pragma unroll
    for (int j = 0; j < 32; j += 8)
        dst[((size_t)(mt + ty + j) * 128 + i) * 128 + ot + tx] = tile[tx][ty + j];
}

// ---------------- level-0 decompose: reads original (B,N,C,K) layout directly ------
__global__ void k_dec0(const float* __restrict__ x,
                       float* __restrict__ xnext, float2* __restrict__ zdst,
                       const float* __restrict__ ecs, const float* __restrict__ ecd) {
    int id = blockIdx.x * blockDim.x + threadIdx.x;
    if (id >= 512 * 4096) return;
    int t = id & 4095;
    int bc = id >> 12;
    int b = bc >> 5, c = bc & 31;
    const float4* pe = (const float4*)(x + (((size_t)b * NSEQ + 2 * t) * 32 + c) * 4);
    const float4* po = (const float4*)(x + (((size_t)b * NSEQ + 2 * t + 1) * 32 + c) * 4);
    float4 e = *pe, o4 = *po;
    float xa[8] = {e.x, e.y, e.z, e.w, o4.x, o4.y, o4.z, o4.w};
    int row0 = bc * 4;
    #pragma unroll
    for (int kp = 0; kp < 4; kp++) {
        float d = 0.f, s = 0.f;
        #pragma unroll
        for (int j = 0; j < 8; j++) {
            d += xa[j] * __ldg(&ecd[j * 4 + kp]);
            s += xa[j] * __ldg(&ecs[j * 4 + kp]);
        }
        size_t o = (size_t)(row0 + kp) * 4096 + t;
        zdst[o] = make_float2(d, s);
        xnext[o] = s;
    }
}

// ---------------- decompose levels 1..6 ------------
__global__ void k_dec(const float* __restrict__ xin, int m,
                      float* __restrict__ xnext, float2* __restrict__ zdst,
                      const float* __restrict__ ecs, const float* __restrict__ ecd) {
    int id = blockIdx.x * blockDim.x + threadIdx.x;
    if (id >= 512 * m) return;
    int t = id % m;
    int bc = id / m;
    int row0 = bc * 4;
    int n = 2 * m;
    float xa[8];
    #pragma unroll
    for (int k = 0; k < 4; k++) {
        float2 v = *((const float2*)(xin + (size_t)(row0 + k) * n) + t);
        xa[k]     = v.x;
        xa[4 + k] = v.y;
    }
    #pragma unroll
    for (int kp = 0; kp < 4; kp++) {
        float d = 0.f, s = 0.f;
        #pragma unroll
        for (int j = 0; j < 8; j++) {
            d += xa[j] * __ldg(&ecd[j * 4 + kp]);
            s += xa[j] * __ldg(&ecs[j * 4 + kp]);
        }
        size_t o = (size_t)(row0 + kp) * m + t;
        zdst[o] = make_float2(d, s);
        xnext[o] = s;
    }
}

// ---------------- batched decompose chain, levels 7..12 ----------------------------
__global__ void __launch_bounds__(32) k_dec_tail(const float* __restrict__ xin,
                                                 const float* __restrict__ ecs,
                                                 const float* __restrict__ ecd) {
    __shared__ float sx[4][64];
    int bc = blockIdx.x;
    int tid = threadIdx.x;
    for (int i = tid; i < 256; i += 32)
        sx[i >> 6][i & 63] = xin[(size_t)(bc * 4 + (i >> 6)) * 64 + (i & 63)];
    __syncthreads();
    int m = 32;
    for (int lev = 7; lev <= 12; lev++) {
        float dv[4], sv[4];
        if (tid < m) {
            float xa[8];
            #pragma unroll
            for (int k = 0; k < 4; k++) {
                xa[k]     = sx[k][2 * tid];
                xa[4 + k] = sx[k][2 * tid + 1];
            }
            #pragma unroll
            for (int kp = 0; kp < 4; kp++) {
                float d = 0.f, s = 0.f;
                #pragma unroll
                for (int j = 0; j < 8; j++) {
                    d += xa[j] * __ldg(&ecd[j * 4 + kp]);
                    s += xa[j] * __ldg(&ecs[j * 4 + kp]);
                }
                dv[kp] = d; sv[kp] = s;
            }
        }
        __syncthreads();
        if (tid < m) {
            float2* z = g_zall + (size_t)c_zoff[lev] * SEQ;
            #pragma unroll
            for (int kp = 0; kp < 4; kp++) {
                z[(size_t)(bc * 4 + kp) * m + tid] = make_float2(dv[kp], sv[kp]);
                sx[kp][tid] = sv[kp];
            }
        }
        __syncthreads();
        m >>= 1;
    }
    if (tid == 0) {
        #pragma unroll
        for (int kp = 0; kp < 4; kp++) g_xfin[bc * 4 + kp] = sx[kp][0];
    }
}

// ================= register-resident warp FFT-128 (DIF, output bit-reversed) ==========
struct Tw7 { float2 wA, wB, w32, w16, w8, w4, w2; };

__device__ __forceinline__ Tw7 make_tw7(int L) {
    Tw7 t;
    t.wA  = __ldg(&g_tw[L * 32]);
    t.wB  = __ldg(&g_tw[(L + 32) * 32]);
    t.w32 = __ldg(&g_tw[L * 64]);
    t.w16 = __ldg(&g_tw[(L & 15) * 128]);
    t.w8  = __ldg(&g_tw[(L & 7) * 256]);
    t.w4  = __ldg(&g_tw[(L & 3) * 512]);
    t.w2  = __ldg(&g_tw[(L & 1) * 1024]);
    return t;
}

__device__ __forceinline__ void cross_stage(float2& x, int bit, float2 w, int L) {
    float ox = __shfl_xor_sync(0xFFFFFFFFu, x.x, bit);
    float oy = __shfl_xor_sync(0xFFFFFFFFu, x.y, bit);
    if (L & bit) x = cmul(make_float2(ox - x.x, oy - x.y), w);
    else         x = make_float2(x.x + ox, x.y + oy);
}
__device__ __forceinline__ void cross_last(float2& x, int L) {
    float ox = __shfl_xor_sync(0xFFFFFFFFu, x.x, 1);
    float oy = __shfl_xor_sync(0xFFFFFFFFu, x.y, 1);
    if (L & 1) x = make_float2(ox - x.x, oy - x.y);
    else       x = make_float2(x.x + ox, x.y + oy);
}

__device__ __forceinline__ void fft128(float2 v[4], const Tw7& tw, int L) {
    float2 a, b;
    a = v[0]; b = v[2]; v[0] = cadd(a, b); v[2] = cmul(csub(a, b), tw.wA);
    a = v[1]; b = v[3]; v[1] = cadd(a, b); v[3] = cmul(csub(a, b), tw.wB);
    a = v[0]; b = v[1]; v[0] = cadd(a, b); v[1] = cmul(csub(a, b), tw.w32);
    a = v[2]; b = v[3]; v[2] = cadd(a, b); v[3] = cmul(csub(a, b), tw.w32);
    #pragma unroll
    for (int j = 0; j < 4; j++) cross_stage(v[j], 16, tw.w16, L);
    #pragma unroll
    for (int j = 0; j < 4; j++) cross_stage(v[j], 8, tw.w8, L);
    #pragma unroll
    for (int j = 0; j < 4; j++) cross_stage(v[j], 4, tw.w4, L);
    #pragma unroll
    for (int j = 0; j < 4; j++) cross_stage(v[j], 2, tw.w2, L);
    #pragma unroll
    for (int j = 0; j < 4; j++) cross_last(v[j], L);
}

// ---------------- pruned forward ----------------------------------------------------
template<int M, int SPB>
__global__ void __launch_bounds__(256) k_pfwd(const float2* __restrict__ zin0,
                                              int modeoff, int l) {
    constexpr int m = 128 * M;
    constexpr int R = 32 / M;
    constexpr int PADM = m + (m >> 5);
    extern __shared__ float2 sm[];
    float2* xin  = sm;
    float2* ybuf = sm + SPB * PADM;
    int tid = threadIdx.x, L = tid & 31, w = tid >> 5;
    int sbase = blockIdx.x * SPB;

    for (int t = tid; t < SPB * m; t += 256) {
        int ss = t / m, tt = t - ss * m;
        xin[ss * PADM + tt + (tt >> 5)] = zin0[(size_t)(sbase + ss) * m + tt];
    }
    Tw7 tw = make_tw7(L);
    __syncthreads();

    #pragma unroll
    for (int r = 0; r < ((M + 7) >> 3); r++) {
        int ss = (M >= 8) ? 0 : (w / M);
        int t2 = (M >= 8) ? ((r << 3) + w) : (w - ss * M);
        float2 v[4];
        const float2* xb = xin + ss * PADM;
        #pragma unroll
        for (int j = 0; j < 4; j++) {
            int t = M * (32 * j + L) + t2;
            v[j] = xb[t + (t >> 5)];
        }
        fft128(v, tw, L);
        #pragma unroll
        for (int j = 0; j < 4; j++) {
            int p = 32 * j + L;
            int q = (int)(__brev((unsigned)p) >> 25);
            ybuf[ss * m + t2 * 128 + q] = v[j];
        }
    }
    __syncthreads();

    for (int p = tid; p < SPB * 128; p += 256) {
        int ss = p >> 7, k = p & 127;
        if (k >= l) continue;
        int k2 = (128 - k) & 127;
        const float2* yb = ybuf + ss * m;
        float2 Xk = make_float2(0.f, 0.f), Xm = make_float2(0.f, 0.f);
        int step = (k * R) & 4095;
        int idx = 0;
        for (int t2 = 0; t2 < M; t2++) {
            float2 wtw = lut4096(idx);
            Xk = cadd(Xk, cmul(wtw, yb[t2 * 128 + k]));
            Xm = cadd(Xm, cmul(cconj(wtw), yb[t2 * 128 + k2]));
            idx = (idx + step) & 4095;
        }
        int s = sbase + ss;
        float2 Df = make_float2(0.5f * (Xk.x + Xm.x), 0.5f * (Xk.y - Xm.y));
        float2 Sf = make_float2(0.5f * (Xk.y + Xm.y), 0.5f * (Xm.x - Xk.x));
        g_Df[(size_t)(modeoff + k) * SEQ + s] = Df;
        g_Sf[(size_t)(modeoff + k) * SEQ + s] = Sf;
    }
}

// ---------------- pruned inverse ----------------------------------------------------
template<int M, int SPB>
__global__ void __launch_bounds__(256) k_pinv(int pudoff, int l, size_t uoff) {
    constexpr int m = 128 * M;
    constexpr int R = 32 / M;
    constexpr int PADM = m + (m >> 5);
    extern __shared__ float2 sm[];
    float2* zbuf  = sm;
    float2* zmbuf = sm + SPB * 128;
    float2* obuf  = sm + SPB * 256;
    int tid = threadIdx.x, L = tid & 31, w = tid >> 5;
    int sbase = blockIdx.x * SPB;

    for (int p = tid; p < SPB * 128; p += 256) {
        int ss = p >> 7, j = p & 127;
        int s = sbase + ss;
        float2 zb = make_float2(0.f, 0.f), zm = make_float2(0.f, 0.f);
        if (j < l) {
            float2 a = g_pud[(size_t)(pudoff + j) * SEQ + s];
            float2 c = g_pus[(size_t)(pudoff + j) * SEQ + s];
            float udx = a.x, udy = a.y, usx = c.x, usy = c.y;
            if (j == 0 || 2 * j == m) { zb = make_float2(udx, usx); }
            else { zb = make_float2(udx - usy, udy + usx);
                   zm = make_float2(udx + usy, usx - udy); }
        }
        zbuf[p] = zb; zmbuf[p] = zm;
    }
    Tw7 tw = make_tw7(L);
    __syncthreads();

    const float inv = 1.0f / (float)m;
    #pragma unroll
    for (int r = 0; r < ((M + 7) >> 3); r++) {
        int ss = (M >= 8) ? 0 : (w / M);
        int t2 = (M >= 8) ? ((r << 3) + w) : (w - ss * M);
        float2 v[4];
        if (M == 1) {
            #pragma unroll
            for (int j = 0; j < 4; j++) {
                int q = 32 * j + L;
                float2 G = (q <= 64) ? zbuf[ss * 128 + q] : zmbuf[ss * 128 + (128 - q)];
                v[j] = cconj(G);
            }
        } else {
            float2 cf = cconj(lut4096((t2 * (4096 / M)) & 4095));
            #pragma unroll
            for (int j = 0; j < 4; j++) {
                int q = 32 * j + L;
                float2 t = cadd(cconj(zbuf[ss * 128 + q]),
                                cmul(cf, cconj(zmbuf[ss * 128 + ((128 - q) & 127)])));
                v[j] = cmul(lut4096((q * t2 * R) & 4095), t);
            }
        }
        fft128(v, tw, L);
        float2* ob = obuf + ss * PADM;
        #pragma unroll
        for (int j = 0; j < 4; j++) {
            int p = 32 * j + L;
            int u = (int)(__brev((unsigned)p) >> 25);
            int t = M * u + t2;
            ob[t + (t >> 5)] = make_float2(v[j].x * inv, -v[j].y * inv);
        }
    }
    __syncthreads();

    for (int t = tid; t < SPB * m; t += 256) {
        int ss = t / m, tt = t - ss * m;
        float2 vv = obuf[ss * PADM + tt + (tt >> 5)];
        size_t o = uoff + (size_t)(sbase + ss) * m + tt;
        g_Ud[o] = vv.x;
        g_Us[o] = vv.y;
    }
}

// ---------------- generic small FFT (shared mem, sincosf; m <= 64 only) ------------
__device__ __forceinline__ void fft_sm(float2* sb, int m, int logm, float sgn) {
    int T = blockDim.x;
    for (int st = 1; st <= logm; st++) {
        int half = 1 << (st - 1);
        float scale = sgn * 6.283185307179586f / (float)(1 << st);
        for (int idx = threadIdx.x; idx < (m >> 1); idx += T) {
            int j = idx & (half - 1);
            int pos = ((idx >> (st - 1)) << st) + j;
            float sw, cw;
            sincosf(scale * (float)j, &sw, &cw);
            float2 u = sb[pos], v = sb[pos + half];
            float2 tv = make_float2(v.x * cw - v.y * sw, v.x * sw + v.y * cw);
            sb[pos]        = make_float2(u.x + tv.x, u.y + tv.y);
            sb[pos + half] = make_float2(u.x - tv.x, u.y - tv.y);
        }
        __syncthreads();
    }
}

// ---------------- batched forward FFT for levels 6..12 -----------------------------
__global__ void k_fftf_tail() {
    __shared__ float2 sb[64];
    int ly = blockIdx.y;
    int lev = 6 + ly;
    int m = 64 >> ly, logm = 6 - ly;
    int l = c_l[lev];
    int modeoff = c_modeoff[lev];
    int s = blockIdx.x;
    const float2* zin = g_zall + (size_t)c_zoff[lev] * SEQ + (size_t)s * m;
    for (int t = threadIdx.x; t < m; t += 32) {
        int r = logm ? (int)(__brev((unsigned)t) >> (32 - logm)) : 0;
        sb[r] = zin[t];
    }
    __syncthreads();
    fft_sm(sb, m, logm, -1.0f);
    for (int k = threadIdx.x; k < l; k += 32) {
        float2 Zk = sb[k];
        float2 Zm = sb[(m - k) & (m - 1)];
        float2 Df = make_float2(0.5f * (Zk.x + Zm.x), 0.5f * (Zk.y - Zm.y));
        float2 Sf = make_float2(0.5f * (Zk.y + Zm.y), 0.5f * (Zm.x - Zk.x));
        g_Df[(size_t)(modeoff + k) * SEQ + s] = Df;
        g_Sf[(size_t)(modeoff + k) * SEQ + s] = Sf;
    }
}

// ---------------- single-launch mixing, full i-contraction, packed f32x2 -----------
__global__ void __launch_bounds__(128) k_mix_all() {
    __shared__ float sdx[128][18], sdy[128][18], ssx[128][18], ssy[128][18];
    int blk = blockIdx.x;
    int lev = 0;
    #pragma unroll
    for (int i = 1; i < 13; i++) if (blk >= c_mixblk[i]) lev = i;
    int mode = blk - c_mixblk[lev];
    int modeoff = c_modeoff[lev];

    // load spectra: 16 batches x 128 input channels
    for (int idx = threadIdx.x; idx < 2048; idx += 128) {
        int b = idx >> 7, ii = idx & 127;
        size_t src = (size_t)(modeoff + mode) * SEQ + b * 128 + ii;
        float2 df = g_Df[src];
        float2 sf = g_Sf[src];
        sdx[ii][b] = df.x; sdy[ii][b] = df.y;
        ssx[ii][b] = sf.x; ssy[ii][b] = sf.y;
    }
    __syncthreads();

    int o = threadIdx.x;
    ull udr[8], udi[8], usr[8], usi[8];
    #pragma unroll
    for (int p = 0; p < 8; p++) { udr[p] = udi[p] = usr[p] = usi[p] = 0ull; }

    for (int ii = 0; ii < 128; ii++) {
        size_t widx = ((size_t)mode * 128 + ii) * 128 + o;
        float ar = __ldg(&g_wt[widx]),          ai = __ldg(&g_wt[W3 + widx]);
        float br = __ldg(&g_wt[2 * W3 + widx]), bi = __ldg(&g_wt[3 * W3 + widx]);
        float cr = __ldg(&g_wt[4 * W3 + widx]), ci = __ldg(&g_wt[5 * W3 + widx]);
        ull arr = bcast2(ar), aii = bcast2(ai), nai = bcast2(-ai);
        ull brr = bcast2(br), bii = bcast2(bi), nbi = bcast2(-bi);
        ull crr = bcast2(cr), cii = bcast2(ci), nci = bcast2(-ci);
        const ull* dxp = (const ull*)&sdx[ii][0];
        const ull* dyp = (const ull*)&sdy[ii][0];
        const ull* sxp = (const ull*)&ssx[ii][0];
        const ull* syp = (const ull*)&ssy[ii][0];
        #pragma unroll
        for (int p = 0; p < 8; p++) {
            ull dx = dxp[p], dy = dyp[p], sx = sxp[p], sy = syp[p];
            udr[p] = fma2(dx, arr, udr[p]); udr[p] = fma2(dy, nai, udr[p]);
            udr[p] = fma2(sx, brr, udr[p]); udr[p] = fma2(sy, nbi, udr[p]);
            udi[p] = fma2(dx, aii, udi[p]); udi[p] = fma2(dy, arr, udi[p]);
            udi[p] = fma2(sx, bii, udi[p]); udi[p] = fma2(sy, brr, udi[p]);
            usr[p] = fma2(dx, crr, usr[p]); usr[p] = fma2(dy, nci, usr[p]);
            usi[p] = fma2(dx, cii, usi[p]); usi[p] = fma2(dy, crr, usi[p]);
        }
    }

    size_t base = (size_t)(modeoff + mode) * SEQ + o;
    #pragma unroll
    for (int p = 0; p < 8; p++) {
        g_pud[base + (2 * p) * 128]     = make_float2(lo32(udr[p]), lo32(udi[p]));
        g_pud[base + (2 * p + 1) * 128] = make_float2(hi32(udr[p]), hi32(udi[p]));
        g_pus[base + (2 * p) * 128]     = make_float2(lo32(usr[p]), lo32(usi[p]));
        g_pus[base + (2 * p + 1) * 128] = make_float2(hi32(usr[p]), hi32(usi[p]));
    }
}

// ---------------- batched inverse FFT for levels 6..12 -----------------------------
__global__ void k_ffti_tail() {
    __shared__ float2 sb[64];
    int ly = blockIdx.y;
    int lev = 6 + ly;
    int m = 64 >> ly, logm = 6 - ly;
    int l = c_l[lev], pudoff = c_modeoff[lev];
    int s = blockIdx.x;
    for (int k = threadIdx.x; k < m; k += 32) {
        float2 Z = make_float2(0.f, 0.f);
        int j = -1, cj = 0;
        if (k < l) { j = k; }
        else { int jm = m - k; if (jm < l) { j = jm; cj = 1; } }
        if (j >= 0) {
            float2 a = g_pud[(size_t)(pudoff + j) * SEQ + s];
            float2 c = g_pus[(size_t)(pudoff + j) * SEQ + s];
            float udx = a.x, udy = a.y, usx = c.x, usy = c.y;
            if (!cj) {
                if (j == 0 || 2 * j == m) Z = make_float2(udx, usx);
                else                      Z = make_float2(udx - usy, udy + usx);
            } else {
                Z = make_float2(udx + usy, usx - udy);
            }
        }
        int r = logm ? (int)(__brev((unsigned)k) >> (32 - logm)) : 0;
        sb[r] = Z;
    }
    __syncthreads();
    fft_sm(sb, m, logm, +1.0f);
    float inv = 1.0f / (float)m;
    float* pud = g_Ud + (size_t)c_zoff[lev] * SEQ + (size_t)s * m;
    float* pus = g_Us + (size_t)c_zoff[lev] * SEQ + (size_t)s * m;
    for (int t = threadIdx.x; t < m; t += 32) {
        float2 v = sb[t];
        pud[t] = v.x * inv;
        pus[t] = v.y * inv;
    }
}

// ---------------- batched T0 + reconstruction chain, levels 12..7 ------------------
__global__ void __launch_bounds__(32) k_rec_tail(const float* __restrict__ t0w,
                                                 const float* __restrict__ t0b,
                                                 const float* __restrict__ rce,
                                                 const float* __restrict__ rco,
                                                 float* __restrict__ xout) {
    __shared__ float sx[4][64];
    int bc = blockIdx.x;
    int tid = threadIdx.x;
    if (tid == 0) {
        float v[4];
        #pragma unroll
        for (int k = 0; k < 4; k++) v[k] = g_xfin[bc * 4 + k];
        #pragma unroll
        for (int kp = 0; kp < 4; kp++) {
            float a = __ldg(&t0b[kp]);
            #pragma unroll
            for (int k = 0; k < 4; k++) a += v[k] * __ldg(&t0w[kp * 4 + k]);
            sx[kp][0] = a;
        }
    }
    __syncthreads();
    int m = 1;
    for (int lev = 12; lev >= 7; lev--) {
        float ev[4], ov[4];
        if (tid < m) {
            float xs[4], ud[4];
            size_t off = (size_t)c_zoff[lev] * SEQ;
            #pragma unroll
            for (int k = 0; k < 4; k++) {
                size_t o = off + (size_t)(bc * 4 + k) * m + tid;
                xs[k] = sx[k][tid] + g_Us[o];
                ud[k] = g_Ud[o];
            }
            #pragma unroll
            for (int kp = 0; kp < 4; kp++) {
                float e = 0.f, o = 0.f;
                #pragma unroll
                for (int j = 0; j < 4; j++) {
                    e += xs[j] * __ldg(&rce[j * 4 + kp]) + ud[j] * __ldg(&rce[(4 + j) * 4 + kp]);
                    o += xs[j] * __ldg(&rco[j * 4 + kp]) + ud[j] * __ldg(&rco[(4 + j) * 4 + kp]);
                }
                ev[kp] = e; ov[kp] = o;
            }
        }
        __syncthreads();
        if (tid < m) {
            #pragma unroll
            for (int kp = 0; kp < 4; kp++) {
                sx[kp][2 * tid]     = ev[kp];
                sx[kp][2 * tid + 1] = ov[kp];
            }
        }
        __syncthreads();
        m <<= 1;
    }
    for (int i = tid; i < 256; i += 32)
        xout[(size_t)(bc * 4 + (i >> 6)) * 64 + (i & 63)] = sx[i >> 6][i & 63];
}

// ---------------- reconstruction levels 6..0 ----------------
__global__ void k_rec(const float* __restrict__ rin, int m, size_t off,
                      float* __restrict__ rout, int final_,
                      const float* __restrict__ rce, const float* __restrict__ rco) {
    int id = blockIdx.x * blockDim.x + threadIdx.x;
    if (id >= 512 * m) return;
    int t = id % m;
    int bc = id / m;
    int row0 = bc * 4;
    float xs[4], ud[4];
    #pragma unroll
    for (int k = 0; k < 4; k++) {
        size_t o = (size_t)(row0 + k) * m + t;
        xs[k] = rin[o] + g_Us[off + o];
        ud[k] = g_Ud[off + o];
    }
    float ev[4], ov[4];
    #pragma unroll
    for (int kp = 0; kp < 4; kp++) {
        float e = 0.f, o = 0.f;
        #pragma unroll
        for (int j = 0; j < 4; j++) {
            e += xs[j] * __ldg(&rce[j * 4 + kp]) + ud[j] * __ldg(&rce[(4 + j) * 4 + kp]);
            o += xs[j] * __ldg(&rco[j * 4 + kp]) + ud[j] * __ldg(&rco[(4 + j) * 4 + kp]);
        }
        ev[kp] = e; ov[kp] = o;
    }
    if (final_) {
        int b = bc >> 5, c = bc & 31;
        float* p0 = rout + (((size_t)b * NSEQ + 2 * t) * 32 + c) * 4;
        *((float4*)p0)         = make_float4(ev[0], ev[1], ev[2], ev[3]);
        *((float4*)(p0 + 128)) = make_float4(ov[0], ov[1], ov[2], ov[3]);
    } else {
        #pragma unroll
        for (int kp = 0; kp < 4; kp++) {
            size_t o = (size_t)(row0 + kp) * (2 * m);
            *((float2*)(rout + o) + t) = make_float2(ev[kp], ov[kp]);
        }
    }
}

// ---------------- host orchestration ----------------
extern "C" void kernel_launch(void* const* d_in, const int* in_sizes, int n_in,
                              void* d_out, int out_size) {
    const float* x   = (const float*)d_in[0];
    const float* wAr = (const float*)d_in[1];
    const float* wAi = (const float*)d_in[2];
    const float* wBr = (const float*)d_in[3];
    const float* wBi = (const float*)d_in[4];
    const float* wCr = (const float*)d_in[5];
    const float* wCi = (const float*)d_in[6];
    const float* ecs = (const float*)d_in[7];
    const float* ecd = (const float*)d_in[8];
    const float* rce = (const float*)d_in[9];
    const float* rco = (const float*)d_in[10];
    const float* t0w = (const float*)d_in[11];
    const float* t0b = (const float*)d_in[12];
    float* out = (float*)d_out;

    float *p_xt, *p_x0, *p_x1; float2 *p_z, *p_zall;
    cudaGetSymbolAddress((void**)&p_xt,   g_xt);
    cudaGetSymbolAddress((void**)&p_x0,   g_x0);
    cudaGetSymbolAddress((void**)&p_x1,   g_x1);
    cudaGetSymbolAddress((void**)&p_z,    g_z);
    cudaGetSymbolAddress((void**)&p_zall, g_zall);

    cudaFuncSetAttribute(k_pfwd<32,1>, cudaFuncAttributeMaxDynamicSharedMemorySize, 70000);

    k_tw<<<8, 256>>>();
    k_wt<<<dim3(16, 128, 6), dim3(32, 8)>>>(wAr, wAi, wBr, wBi, wCr, wCi);

    // ---- phase 1: decomposition chain ----
    k_dec0<<<(512 * 4096 + 255) / 256, 256>>>(x, p_x0, p_zall + (size_t)h_zoff[0] * SEQ, ecs, ecd);
    for (int lev = 1; lev <= 6; lev++) {
        int m = (NSEQ >> lev) >> 1;
        const float* xin = (lev & 1) ? p_x0 : p_x1;
        float* xnext = (lev & 1) ? p_x1 : p_x0;
        float2* zdst = p_zall + (size_t)h_zoff[lev] * SEQ;
        int tot = 512 * m;
        k_dec<<<(tot + 255) / 256, 256>>>(xin, m, xnext, zdst, ecs, ecd);
    }
    k_dec_tail<<<512, 32>>>(p_x0, ecs, ecd);

    // ---- phase 2: forward FFTs, all levels ----
    {
        auto smF = [](int m, int spb) { return (size_t)(spb * (m + m / 32) + spb * m) * sizeof(float2); };
        k_pfwd<32,1><<<SEQ,     256, smF(4096,1)>>>(p_zall + (size_t)h_zoff[0]*SEQ, h_modeoff[0], h_l[0]);
        k_pfwd<16,1><<<SEQ,     256, smF(2048,1)>>>(p_zall + (size_t)h_zoff[1]*SEQ, h_modeoff[1], h_l[1]);
        k_pfwd<8, 1><<<SEQ,     256, smF(1024,1)>>>(p_zall + (size_t)h_zoff[2]*SEQ, h_modeoff[2], h_l[2]);
        k_pfwd<4, 2><<<SEQ / 2, 256, smF(512, 2)>>>(p_zall + (size_t)h_zoff[3]*SEQ, h_modeoff[3], h_l[3]);
        k_pfwd<2, 4><<<SEQ / 4, 256, smF(256, 4)>>>(p_zall + (size_t)h_zoff[4]*SEQ, h_modeoff[4], h_l[4]);
        k_pfwd<1, 8><<<SEQ / 8, 256, smF(128, 8)>>>(p_zall + (size_t)h_zoff[5]*SEQ, h_modeoff[5], h_l[5]);
        k_fftf_tail<<<dim3(SEQ, 7), 32>>>();
    }

    // ---- phase 3: one mixing launch over all levels, f32x2 packed ----
    k_mix_all<<<775, 128>>>();

    // ---- phase 4: inverse FFTs, all levels ----
    {
        auto smI = [](int m, int spb) { return (size_t)(spb * 256 + spb * (m + m / 32)) * sizeof(float2); };
        k_pinv<32,1><<<SEQ,     256, smI(4096,1)>>>(h_modeoff[0], h_l[0], (size_t)h_zoff[0]*SEQ);
        k_pinv<16,1><<<SEQ,     256, smI(2048,1)>>>(h_modeoff[1], h_l[1], (size_t)h_zoff[1]*SEQ);
        k_pinv<8, 1><<<SEQ,     256, smI(1024,1)>>>(h_modeoff[2], h_l[2], (size_t)h_zoff[2]*SEQ);
        k_pinv<4, 2><<<SEQ / 2, 256, smI(512, 2)>>>(h_modeoff[3], h_l[3], (size_t)h_zoff[3]*SEQ);
        k_pinv<2, 4><<<SEQ / 4, 256, smI(256, 4)>>>(h_modeoff[4], h_l[4], (size_t)h_zoff[4]*SEQ);
        k_pinv<1, 8><<<SEQ / 8, 256, smI(128, 8)>>>(h_modeoff[5], h_l[5], (size_t)h_zoff[5]*SEQ);
        k_ffti_tail<<<dim3(SEQ, 7), 32>>>();
    }

    // ---- phase 5: T0 + rec levels 12..7 in one kernel, then rec 6..0 ----
    k_rec_tail<<<512, 32>>>(t0w, t0b, rce, rco, p_xt);

    float* bufA = p_xt;
    float* bufB = (float*)p_z;
    float* cur = bufA;
    for (int lev = 6; lev >= 0; lev--) {
        int m = (NSEQ >> lev) >> 1;
        size_t off = (size_t)h_zoff[lev] * SEQ;
        int fin = (lev == 0);
        float* rout = fin ? out : ((cur == bufA) ? bufB : bufA);
        int tot = 512 * m;
        k_rec<<<(tot + 255) / 256, 256>>>(cur, m, off, rout, fin, rce, rco);
        if (!fin) cur = rout;
    }
    (void)in_sizes; (void)n_in; (void)out_size;
}

// round 15
// speedup vs baseline: 2.2415x; 1.0836x over previous
#include <cuda_runtime.h>

#define SEQ   2048          // B * CK
#define CKD   128
#define NSEQ  8192
#define W3    (128*128*128)

typedef unsigned long long ull;

// ---------------- static device scratch (no allocations allowed) ----------------
__device__ float  g_xt[SEQ * NSEQ];       // recon buf A
__device__ float2 g_z  [SEQ * 4096];      // recon buf B
__device__ float2 g_zall[SEQ * 8191];     // packed d + i*s, ALL levels (offsets c_zoff)
__device__ float  g_x0 [SEQ * 4096];      // x4 (smooth coeffs after level 4)
__device__ float  g_xfin[SEQ];            // coarsest x (512 bc * 4 k)
__device__ float2 g_Df [775 * SEQ];       // (global mode, s) spectra of d, all levels
__device__ float2 g_Sf [775 * SEQ];       // (global mode, s) spectra of s
__device__ float2 g_pud[775 * SEQ];       // UdF, all levels (offsets c_modeoff)
__device__ float2 g_pus[775 * SEQ];       // UsF
__device__ float  g_wt [6 * W3];          // weights transposed to (w, mode, i, o)
__device__ float  g_Ud [SEQ * 8191];      // detail outputs, all levels
__device__ float  g_Us [SEQ * 8191];      // smooth outputs, all levels
__device__ float2 g_tw [2048];            // tw[x] = exp(-2*pi*i*x/4096)

// ---------------- per-level tables ----------------
__constant__ int c_l[13]       = {128,128,128,128,128,65,33,17,9,5,3,2,1};
__constant__ int c_modeoff[13] = {0,128,256,384,512,640,705,738,755,764,769,772,774};
__constant__ int c_mixblk[14]  = {0,128,256,384,512,640,705,738,755,764,769,772,774,775};
__constant__ int c_zoff[13]    = {0,4096,6144,7168,7680,7936,8064,8128,8160,8176,8184,8188,8190};
// merged FFT launch: levels 0..5 pruned (2048,2048,2048,1024,512,256 blocks), levels 6..12 tail (256 blocks each)
__constant__ int c_pfblk[14]   = {0,2048,4096,6144,7168,7680,7936,8192,8448,8704,8960,9216,9472,9728};

static const int h_zoff[13]    = {0,4096,6144,7168,7680,7936,8064,8128,8160,8176,8184,8188,8190};

// ---------------- complex / packed helpers ----------------
__device__ __forceinline__ float2 cadd(float2 a, float2 b){ return make_float2(a.x+b.x, a.y+b.y); }
__device__ __forceinline__ float2 csub(float2 a, float2 b){ return make_float2(a.x-b.x, a.y-b.y); }
__device__ __forceinline__ float2 cmul(float2 a, float2 b){
    return make_float2(fmaf(a.x, b.x, -a.y*b.y), fmaf(a.x, b.y, a.y*b.x));
}
__device__ __forceinline__ float2 cconj(float2 a){ return make_float2(a.x, -a.y); }
__device__ __forceinline__ float2 lut4096(int x){
    float2 t = __ldg(&g_tw[x & 2047]);
    if (x & 2048) { t.x = -t.x; t.y = -t.y; }
    return t;
}
__device__ __forceinline__ ull fma2(ull a, ull b, ull c){
    ull d;
    asm("fma.rn.f32x2 %0, %1, %2, %3;" : "=l"(d) : "l"(a), "l"(b), "l"(c));
    return d;
}
__device__ __forceinline__ ull bcast2(float w){
    ull d;
    asm("mov.b64 %0, {%1, %1};" : "=l"(d) : "f"(w));
    return d;
}
__device__ __forceinline__ float lo32(ull v){ return __uint_as_float((unsigned)(v & 0xffffffffull)); }
__device__ __forceinline__ float hi32(ull v){ return __uint_as_float((unsigned)(v >> 32)); }

// ---------------- twiddle table ----------------
__global__ void k_tw() {
    int x = blockIdx.x * blockDim.x + threadIdx.x;
    if (x >= 2048) return;
    float ang = -6.283185307179586f * (float)x / 4096.0f;
    float s, c;
    sincosf(ang, &s, &c);
    g_tw[x] = make_float2(c, s);
}

// ---------------- weight transpose: (i,o,mode) -> (mode,i,o) ----------------
__global__ void k_wt(const float* __restrict__ wAr, const float* __restrict__ wAi,
                     const float* __restrict__ wBr, const float* __restrict__ wBi,
                     const float* __restrict__ wCr, const float* __restrict__ wCi) {
    __shared__ float tile[32][33];
    int w = blockIdx.z;
    int i = blockIdx.y;
    int ot = (blockIdx.x >> 2) << 5;
    int mt = (blockIdx.x & 3) << 5;
    const float* src;
    switch (w) {
        case 0: src = wAr; break; case 1: src = wAi; break;
        case 2: src = wBr; break; case 3: src = wBi; break;
        case 4: src = wCr; break; default: src = wCi; break;
    }
    int tx = threadIdx.x, ty = threadIdx.y;
    #pragma unroll
    for (int j = 0; j < 32; j += 8)
        tile[ty + j][tx] = src[((size_t)i * 128 + ot + ty + j) * 128 + mt + tx];
    __syncthreads();
    float* dst = g_wt + (size_t)w * W3;
    #pragma unroll
    for (int j = 0; j < 32; j += 8)
        dst[((size_t)(mt + ty + j) * 128 + i) * 128 + ot + tx] = tile[tx][ty + j];
}

// ---------------- fused decompose, levels 0..4 (fully parallel, coalesced input) ----
// Block = (b, 32-sample n-tile). Non-overlapping 2-tap filters: everything in smem.
__global__ void __launch_bounds__(256) k_dec05(const float* __restrict__ x,
                                               const float* __restrict__ ecs,
                                               const float* __restrict__ ecd,
                                               float* __restrict__ x4) {
    __shared__ float si[128][33];   // [ck][n_local]
    __shared__ float s0[128][17];   // smooth after lvl0: [ck][t0]
    __shared__ float s1[128][9];
    __shared__ float s2[128][5];
    __shared__ float s3[128][3];
    int b = blockIdx.x >> 8;
    int tile = blockIdx.x & 255;
    int tid = threadIdx.x;
    const float* src = x + ((size_t)b * NSEQ + (size_t)tile * 32) * 128;
    #pragma unroll
    for (int i = 0; i < 16; i++) {
        int idx = tid + i * 256;                 // 32 n x 128 ck
        si[idx & 127][idx >> 7] = src[idx];      // coalesced read, conflict-free store
    }
    __syncthreads();
    // ---- level 0: 512 items (c, t0), t0 in [0,16) ----
    for (int it = tid; it < 512; it += 256) {
        int c = it >> 4, t0 = it & 15;
        float xa[8];
        #pragma unroll
        for (int k = 0; k < 4; k++) {
            xa[k]     = si[c*4+k][2*t0];
            xa[4 + k] = si[c*4+k][2*t0+1];
        }
        int row0 = (b * 32 + c) * 4;
        int tg = tile * 16 + t0;
        #pragma unroll
        for (int kp = 0; kp < 4; kp++) {
            float d = 0.f, s = 0.f;
            #pragma unroll
            for (int j = 0; j < 8; j++) {
                d += xa[j] * __ldg(&ecd[j*4+kp]);
                s += xa[j] * __ldg(&ecs[j*4+kp]);
            }
            g_zall[(size_t)(row0 + kp) * 4096 + tg] = make_float2(d, s);
            s0[c*4+kp][t0] = s;
        }
    }
    __syncthreads();
    // ---- level 1: 256 items ----
    {
        int c = tid >> 3, t1 = tid & 7;
        float xa[8];
        #pragma unroll
        for (int k = 0; k < 4; k++) {
            xa[k]     = s0[c*4+k][2*t1];
            xa[4 + k] = s0[c*4+k][2*t1+1];
        }
        int row0 = (b * 32 + c) * 4;
        int tg = tile * 8 + t1;
        #pragma unroll
        for (int kp = 0; kp < 4; kp++) {
            float d = 0.f, s = 0.f;
            #pragma unroll
            for (int j = 0; j < 8; j++) {
                d += xa[j] * __ldg(&ecd[j*4+kp]);
                s += xa[j] * __ldg(&ecs[j*4+kp]);
            }
            g_zall[(size_t)4096 * SEQ + (size_t)(row0 + kp) * 2048 + tg] = make_float2(d, s);
            s1[c*4+kp][t1] = s;
        }
    }
    __syncthreads();
    // ---- level 2: 128 items ----
    if (tid < 128) {
        int c = tid >> 2, t2 = tid & 3;
        float xa[8];
        #pragma unroll
        for (int k = 0; k < 4; k++) {
            xa[k]     = s1[c*4+k][2*t2];
            xa[4 + k] = s1[c*4+k][2*t2+1];
        }
        int row0 = (b * 32 + c) * 4;
        int tg = tile * 4 + t2;
        #pragma unroll
        for (int kp = 0; kp < 4; kp++) {
            float d = 0.f, s = 0.f;
            #pragma unroll
            for (int j = 0; j < 8; j++) {
                d += xa[j] * __ldg(&ecd[j*4+kp]);
                s += xa[j] * __ldg(&ecs[j*4+kp]);
            }
            g_zall[(size_t)6144 * SEQ + (size_t)(row0 + kp) * 1024 + tg] = make_float2(d, s);
            s2[c*4+kp][t2] = s;
        }
    }
    __syncthreads();
    // ---- level 3: 64 items ----
    if (tid < 64) {
        int c = tid >> 1, t3 = tid & 1;
        float xa[8];
        #pragma unroll
        for (int k = 0; k < 4; k++) {
            xa[k]     = s2[c*4+k][2*t3];
            xa[4 + k] = s2[c*4+k][2*t3+1];
        }
        int row0 = (b * 32 + c) * 4;
        int tg = tile * 2 + t3;
        #pragma unroll
        for (int kp = 0; kp < 4; kp++) {
            float d = 0.f, s = 0.f;
            #pragma unroll
            for (int j = 0; j < 8; j++) {
                d += xa[j] * __ldg(&ecd[j*4+kp]);
                s += xa[j] * __ldg(&ecs[j*4+kp]);
            }
            g_zall[(size_t)7168 * SEQ + (size_t)(row0 + kp) * 512 + tg] = make_float2(d, s);
            s3[c*4+kp][t3] = s;
        }
    }
    __syncthreads();
    // ---- level 4: 32 items, writes x4 to global ----
    if (tid < 32) {
        int c = tid;
        float xa[8];
        #pragma unroll
        for (int k = 0; k < 4; k++) {
            xa[k]     = s3[c*4+k][0];
            xa[4 + k] = s3[c*4+k][1];
        }
        int row0 = (b * 32 + c) * 4;
        #pragma unroll
        for (int kp = 0; kp < 4; kp++) {
            float d = 0.f, s = 0.f;
            #pragma unroll
            for (int j = 0; j < 8; j++) {
                d += xa[j] * __ldg(&ecd[j*4+kp]);
                s += xa[j] * __ldg(&ecs[j*4+kp]);
            }
            g_zall[(size_t)7680 * SEQ + (size_t)(row0 + kp) * 256 + tile] = make_float2(d, s);
            x4[(size_t)(row0 + kp) * 256 + tile] = s;
        }
    }
}

// ---------------- decompose levels 5..12 chained in smem (one block per bc) --------
__device__ __forceinline__ void dec_step(const float* in, int ins, float* out, int outs,
                                         int mOut, int bc, int lev,
                                         const float* __restrict__ ecs,
                                         const float* __restrict__ ecd) {
    int tid = threadIdx.x;
    if (tid < mOut) {
        float xa[8];
        #pragma unroll
        for (int k = 0; k < 4; k++) {
            xa[k]     = in[k * ins + 2 * tid];
            xa[4 + k] = in[k * ins + 2 * tid + 1];
        }
        float2* z = g_zall + (size_t)c_zoff[lev] * SEQ;
        #pragma unroll
        for (int kp = 0; kp < 4; kp++) {
            float d = 0.f, s = 0.f;
            #pragma unroll
            for (int j = 0; j < 8; j++) {
                d += xa[j] * __ldg(&ecd[j*4+kp]);
                s += xa[j] * __ldg(&ecs[j*4+kp]);
            }
            z[(size_t)(bc * 4 + kp) * mOut + tid] = make_float2(d, s);
            out[kp * outs + tid] = s;
        }
    }
    __syncthreads();
}

__global__ void __launch_bounds__(128) k_dec_rest(const float* __restrict__ x4,
                                                  const float* __restrict__ ecs,
                                                  const float* __restrict__ ecd) {
    __shared__ float si[4][256];
    __shared__ float sA[4][128];
    __shared__ float sB[4][64];
    int bc = blockIdx.x, tid = threadIdx.x;
    for (int i = tid; i < 1024; i += 128)
        si[i >> 8][i & 255] = x4[(size_t)(bc * 4 + (i >> 8)) * 256 + (i & 255)];
    __syncthreads();
    dec_step(&si[0][0], 256, &sA[0][0], 128, 128, bc, 5,  ecs, ecd);
    dec_step(&sA[0][0], 128, &sB[0][0], 64,  64,  bc, 6,  ecs, ecd);
    dec_step(&sB[0][0], 64,  &sA[0][0], 128, 32,  bc, 7,  ecs, ecd);
    dec_step(&sA[0][0], 128, &sB[0][0], 64,  16,  bc, 8,  ecs, ecd);
    dec_step(&sB[0][0], 64,  &sA[0][0], 128, 8,   bc, 9,  ecs, ecd);
    dec_step(&sA[0][0], 128, &sB[0][0], 64,  4,   bc, 10, ecs, ecd);
    dec_step(&sB[0][0], 64,  &sA[0][0], 128, 2,   bc, 11, ecs, ecd);
    dec_step(&sA[0][0], 128, &sB[0][0], 64,  1,   bc, 12, ecs, ecd);
    if (tid == 0) {
        #pragma unroll
        for (int kp = 0; kp < 4; kp++) g_xfin[bc * 4 + kp] = sB[kp][0];
    }
}

// ================= register-resident warp FFT-128 (DIF, output bit-reversed) ==========
struct Tw7 { float2 wA, wB, w32, w16, w8, w4, w2; };

__device__ __forceinline__ Tw7 make_tw7(int L) {
    Tw7 t;
    t.wA  = __ldg(&g_tw[L * 32]);
    t.wB  = __ldg(&g_tw[(L + 32) * 32]);
    t.w32 = __ldg(&g_tw[L * 64]);
    t.w16 = __ldg(&g_tw[(L & 15) * 128]);
    t.w8  = __ldg(&g_tw[(L & 7) * 256]);
    t.w4  = __ldg(&g_tw[(L & 3) * 512]);
    t.w2  = __ldg(&g_tw[(L & 1) * 1024]);
    return t;
}

__device__ __forceinline__ void cross_stage(float2& x, int bit, float2 w, int L) {
    float ox = __shfl_xor_sync(0xFFFFFFFFu, x.x, bit);
    float oy = __shfl_xor_sync(0xFFFFFFFFu, x.y, bit);
    if (L & bit) x = cmul(make_float2(ox - x.x, oy - x.y), w);
    else         x = make_float2(x.x + ox, x.y + oy);
}
__device__ __forceinline__ void cross_last(float2& x, int L) {
    float ox = __shfl_xor_sync(0xFFFFFFFFu, x.x, 1);
    float oy = __shfl_xor_sync(0xFFFFFFFFu, x.y, 1);
    if (L & 1) x = make_float2(ox - x.x, oy - x.y);
    else       x = make_float2(x.x + ox, x.y + oy);
}

__device__ __forceinline__ void fft128(float2 v[4], const Tw7& tw, int L) {
    float2 a, b;
    a = v[0]; b = v[2]; v[0] = cadd(a, b); v[2] = cmul(csub(a, b), tw.wA);
    a = v[1]; b = v[3]; v[1] = cadd(a, b); v[3] = cmul(csub(a, b), tw.wB);
    a = v[0]; b = v[1]; v[0] = cadd(a, b); v[1] = cmul(csub(a, b), tw.w32);
    a = v[2]; b = v[3]; v[2] = cadd(a, b); v[3] = cmul(csub(a, b), tw.w32);
    #pragma unroll
    for (int j = 0; j < 4; j++) cross_stage(v[j], 16, tw.w16, L);
    #pragma unroll
    for (int j = 0; j < 4; j++) cross_stage(v[j], 8, tw.w8, L);
    #pragma unroll
    for (int j = 0; j < 4; j++) cross_stage(v[j], 4, tw.w4, L);
    #pragma unroll
    for (int j = 0; j < 4; j++) cross_stage(v[j], 2, tw.w2, L);
    #pragma unroll
    for (int j = 0; j < 4; j++) cross_last(v[j], L);
}

// ---------------- warp-level small FFT for tail levels (m <= 64) --------------------
__device__ __forceinline__ void fft_w(float2* sb, int m, int logm, float sgn, int lane) {
    for (int st = 1; st <= logm; st++) {
        int half = 1 << (st - 1);
        float scale = sgn * 6.283185307179586f / (float)(1 << st);
        for (int idx = lane; idx < (m >> 1); idx += 32) {
            int j = idx & (half - 1);
            int pos = ((idx >> (st - 1)) << st) + j;
            float sw, cw;
            sincosf(scale * (float)j, &sw, &cw);
            float2 u = sb[pos], v = sb[pos + half];
            float2 tv = make_float2(v.x * cw - v.y * sw, v.x * sw + v.y * cw);
            sb[pos]        = make_float2(u.x + tv.x, u.y + tv.y);
            sb[pos + half] = make_float2(u.x - tv.x, u.y - tv.y);
        }
        __syncwarp();
    }
}

// ---------------- pruned forward body ----------------------------------------------
template<int M, int SPB>
__device__ __forceinline__ void pfwd_body(int blk, float2* sm,
                                          const float2* __restrict__ zin0,
                                          int modeoff, int l) {
    constexpr int m = 128 * M;
    constexpr int R = 32 / M;
    constexpr int PADM = m + (m >> 5);
    float2* xin  = sm;
    float2* ybuf = sm + SPB * PADM;
    int tid = threadIdx.x, L = tid & 31, w = tid >> 5;
    int sbase = blk * SPB;

    for (int t = tid; t < SPB * m; t += 256) {
        int ss = t / m, tt = t - ss * m;
        xin[ss * PADM + tt + (tt >> 5)] = zin0[(size_t)(sbase + ss) * m + tt];
    }
    Tw7 tw = make_tw7(L);
    __syncthreads();

    #pragma unroll
    for (int r = 0; r < ((M + 7) >> 3); r++) {
        int ss = (M >= 8) ? 0 : (w / M);
        int t2 = (M >= 8) ? ((r << 3) + w) : (w - ss * M);
        float2 v[4];
        const float2* xb = xin + ss * PADM;
        #pragma unroll
        for (int j = 0; j < 4; j++) {
            int t = M * (32 * j + L) + t2;
            v[j] = xb[t + (t >> 5)];
        }
        fft128(v, tw, L);
        #pragma unroll
        for (int j = 0; j < 4; j++) {
            int p = 32 * j + L;
            int q = (int)(__brev((unsigned)p) >> 25);
            ybuf[ss * m + t2 * 128 + q] = v[j];
        }
    }
    __syncthreads();

    for (int p = tid; p < SPB * 128; p += 256) {
        int ss = p >> 7, k = p & 127;
        if (k >= l) continue;
        int k2 = (128 - k) & 127;
        const float2* yb = ybuf + ss * m;
        float2 Xk = make_float2(0.f, 0.f), Xm = make_float2(0.f, 0.f);
        int step = (k * R) & 4095;
        int idx = 0;
        for (int t2 = 0; t2 < M; t2++) {
            float2 wtw = lut4096(idx);
            Xk = cadd(Xk, cmul(wtw, yb[t2 * 128 + k]));
            Xm = cadd(Xm, cmul(cconj(wtw), yb[t2 * 128 + k2]));
            idx = (idx + step) & 4095;
        }
        int s = sbase + ss;
        float2 Df = make_float2(0.5f * (Xk.x + Xm.x), 0.5f * (Xk.y - Xm.y));
        float2 Sf = make_float2(0.5f * (Xk.y + Xm.y), 0.5f * (Xm.x - Xk.x));
        g_Df[(size_t)(modeoff + k) * SEQ + s] = Df;
        g_Sf[(size_t)(modeoff + k) * SEQ + s] = Sf;
    }
}

// ---------------- merged forward FFT launch (all 13 levels) -------------------------
__global__ void __launch_bounds__(256) k_pfwd_all() {
    extern __shared__ float2 sm[];
    int blk = blockIdx.x;
    int lev = 0;
    #pragma unroll
    for (int i = 1; i < 14; i++) if (blk >= c_pfblk[i]) lev = i;
    int local = blk - c_pfblk[lev];
    if (lev < 6) {
        const float2* zin0 = g_zall + (size_t)c_zoff[lev] * SEQ;
        int mo = c_modeoff[lev], l = c_l[lev];
        switch (lev) {
            case 0: pfwd_body<32,1>(local, sm, zin0, mo, l); break;
            case 1: pfwd_body<16,1>(local, sm, zin0, mo, l); break;
            case 2: pfwd_body<8, 1>(local, sm, zin0, mo, l); break;
            case 3: pfwd_body<4, 2>(local, sm, zin0, mo, l); break;
            case 4: pfwd_body<2, 4>(local, sm, zin0, mo, l); break;
            default: pfwd_body<1, 8>(local, sm, zin0, mo, l); break;
        }
    } else {
        int w = threadIdx.x >> 5, lane = threadIdx.x & 31;
        int s = local * 8 + w;
        int ly = lev - 6;
        int m = 64 >> ly, logm = 6 - ly;
        float2* sb = sm + w * 64;
        const float2* zin = g_zall + (size_t)c_zoff[lev] * SEQ + (size_t)s * m;
        for (int t = lane; t < m; t += 32) {
            int r = logm ? (int)(__brev((unsigned)t) >> (32 - logm)) : 0;
            sb[r] = zin[t];
        }
        __syncwarp();
        fft_w(sb, m, logm, -1.0f, lane);
        int l = c_l[lev], mo = c_modeoff[lev];
        for (int k = lane; k < l; k += 32) {
            float2 Zk = sb[k];
            float2 Zm = sb[(m - k) & (m - 1)];
            float2 Df = make_float2(0.5f * (Zk.x + Zm.x), 0.5f * (Zk.y - Zm.y));
            float2 Sf = make_float2(0.5f * (Zk.y + Zm.y), 0.5f * (Zm.x - Zk.x));
            g_Df[(size_t)(mo + k) * SEQ + s] = Df;
            g_Sf[(size_t)(mo + k) * SEQ + s] = Sf;
        }
    }
}

// ---------------- pruned inverse body -----------------------------------------------
template<int M, int SPB>
__device__ __forceinline__ void pinv_body(int blk, float2* sm,
                                          int pudoff, int l, size_t uoff) {
    constexpr int m = 128 * M;
    constexpr int R = 32 / M;
    constexpr int PADM = m + (m >> 5);
    float2* zbuf  = sm;
    float2* zmbuf = sm + SPB * 128;
    float2* obuf  = sm + SPB * 256;
    int tid = threadIdx.x, L = tid & 31, w = tid >> 5;
    int sbase = blk * SPB;

    for (int p = tid; p < SPB * 128; p += 256) {
        int ss = p >> 7, j = p & 127;
        int s = sbase + ss;
        float2 zb = make_float2(0.f, 0.f), zm = make_float2(0.f, 0.f);
        if (j < l) {
            float2 a = g_pud[(size_t)(pudoff + j) * SEQ + s];
            float2 c = g_pus[(size_t)(pudoff + j) * SEQ + s];
            float udx = a.x, udy = a.y, usx = c.x, usy = c.y;
            if (j == 0 || 2 * j == m) { zb = make_float2(udx, usx); }
            else { zb = make_float2(udx - usy, udy + usx);
                   zm = make_float2(udx + usy, usx - udy); }
        }
        zbuf[p] = zb; zmbuf[p] = zm;
    }
    Tw7 tw = make_tw7(L);
    __syncthreads();

    const float inv = 1.0f / (float)m;
    #pragma unroll
    for (int r = 0; r < ((M + 7) >> 3); r++) {
        int ss = (M >= 8) ? 0 : (w / M);
        int t2 = (M >= 8) ? ((r << 3) + w) : (w - ss * M);
        float2 v[4];
        if (M == 1) {
            #pragma unroll
            for (int j = 0; j < 4; j++) {
                int q = 32 * j + L;
                float2 G = (q <= 64) ? zbuf[ss * 128 + q] : zmbuf[ss * 128 + (128 - q)];
                v[j] = cconj(G);
            }
        } else {
            float2 cf = cconj(lut4096((t2 * (4096 / M)) & 4095));
            #pragma unroll
            for (int j = 0; j < 4; j++) {
                int q = 32 * j + L;
                float2 t = cadd(cconj(zbuf[ss * 128 + q]),
                                cmul(cf, cconj(zmbuf[ss * 128 + ((128 - q) & 127)])));
                v[j] = cmul(lut4096((q * t2 * R) & 4095), t);
            }
        }
        fft128(v, tw, L);
        float2* ob = obuf + ss * PADM;
        #pragma unroll
        for (int j = 0; j < 4; j++) {
            int p = 32 * j + L;
            int u = (int)(__brev((unsigned)p) >> 25);
            int t = M * u + t2;
            ob[t + (t >> 5)] = make_float2(v[j].x * inv, -v[j].y * inv);
        }
    }
    __syncthreads();

    for (int t = tid; t < SPB * m; t += 256) {
        int ss = t / m, tt = t - ss * m;
        float2 vv = obuf[ss * PADM + tt + (tt >> 5)];
        size_t o = uoff + (size_t)(sbase + ss) * m + tt;
        g_Ud[o] = vv.x;
        g_Us[o] = vv.y;
    }
}

// ---------------- merged inverse FFT launch (all 13 levels) -------------------------
__global__ void __launch_bounds__(256) k_pinv_all() {
    extern __shared__ float2 sm[];
    int blk = blockIdx.x;
    int lev = 0;
    #pragma unroll
    for (int i = 1; i < 14; i++) if (blk >= c_pfblk[i]) lev = i;
    int local = blk - c_pfblk[lev];
    if (lev < 6) {
        int po = c_modeoff[lev], l = c_l[lev];
        size_t uoff = (size_t)c_zoff[lev] * SEQ;
        switch (lev) {
            case 0: pinv_body<32,1>(local, sm, po, l, uoff); break;
            case 1: pinv_body<16,1>(local, sm, po, l, uoff); break;
            case 2: pinv_body<8, 1>(local, sm, po, l, uoff); break;
            case 3: pinv_body<4, 2>(local, sm, po, l, uoff); break;
            case 4: pinv_body<2, 4>(local, sm, po, l, uoff); break;
            default: pinv_body<1, 8>(local, sm, po, l, uoff); break;
        }
    } else {
        int w = threadIdx.x >> 5, lane = threadIdx.x & 31;
        int s = local * 8 + w;
        int ly = lev - 6;
        int m = 64 >> ly, logm = 6 - ly;
        float2* sb = sm + w * 64;
        int l = c_l[lev], po = c_modeoff[lev];
        for (int k = lane; k < m; k += 32) {
            float2 Z = make_float2(0.f, 0.f);
            int j = -1, cj = 0;
            if (k < l) { j = k; }
            else { int jm = m - k; if (jm < l) { j = jm; cj = 1; } }
            if (j >= 0) {
                float2 a = g_pud[(size_t)(po + j) * SEQ + s];
                float2 c = g_pus[(size_t)(po + j) * SEQ + s];
                float udx = a.x, udy = a.y, usx = c.x, usy = c.y;
                if (!cj) {
                    if (j == 0 || 2 * j == m) Z = make_float2(udx, usx);
                    else                      Z = make_float2(udx - usy, udy + usx);
                } else {
                    Z = make_float2(udx + usy, usx - udy);
                }
            }
            int r = logm ? (int)(__brev((unsigned)k) >> (32 - logm)) : 0;
            sb[r] = Z;
        }
        __syncwarp();
        fft_w(sb, m, logm, +1.0f, lane);
        float inv = 1.0f / (float)m;
        float* pud = g_Ud + (size_t)c_zoff[lev] * SEQ + (size_t)s * m;
        float* pus = g_Us + (size_t)c_zoff[lev] * SEQ + (size_t)s * m;
        for (int t = lane; t < m; t += 32) {
            float2 v = sb[t];
            pud[t] = v.x * inv;
            pus[t] = v.y * inv;
        }
    }
}

// ---------------- single-launch mixing, full i-contraction, packed f32x2 -----------
__global__ void __launch_bounds__(128) k_mix_all() {
    __shared__ float sdx[128][18], sdy[128][18], ssx[128][18], ssy[128][18];
    int blk = blockIdx.x;
    int lev = 0;
    #pragma unroll
    for (int i = 1; i < 13; i++) if (blk >= c_mixblk[i]) lev = i;
    int mode = blk - c_mixblk[lev];
    int modeoff = c_modeoff[lev];

    for (int idx = threadIdx.x; idx < 2048; idx += 128) {
        int b = idx >> 7, ii = idx & 127;
        size_t src = (size_t)(modeoff + mode) * SEQ + b * 128 + ii;
        float2 df = g_Df[src];
        float2 sf = g_Sf[src];
        sdx[ii][b] = df.x; sdy[ii][b] = df.y;
        ssx[ii][b] = sf.x; ssy[ii][b] = sf.y;
    }
    __syncthreads();

    int o = threadIdx.x;
    ull udr[8], udi[8], usr[8], usi[8];
    #pragma unroll
    for (int p = 0; p < 8; p++) { udr[p] = udi[p] = usr[p] = usi[p] = 0ull; }

    for (int ii = 0; ii < 128; ii++) {
        size_t widx = ((size_t)mode * 128 + ii) * 128 + o;
        float ar = __ldg(&g_wt[widx]),          ai = __ldg(&g_wt[W3 + widx]);
        float br = __ldg(&g_wt[2 * W3 + widx]), bi = __ldg(&g_wt[3 * W3 + widx]);
        float cr = __ldg(&g_wt[4 * W3 + widx]), ci = __ldg(&g_wt[5 * W3 + widx]);
        ull arr = bcast2(ar), aii = bcast2(ai), nai = bcast2(-ai);
        ull brr = bcast2(br), bii = bcast2(bi), nbi = bcast2(-bi);
        ull crr = bcast2(cr), cii = bcast2(ci), nci = bcast2(-ci);
        const ull* dxp = (const ull*)&sdx[ii][0];
        const ull* dyp = (const ull*)&sdy[ii][0];
        const ull* sxp = (const ull*)&ssx[ii][0];
        const ull* syp = (const ull*)&ssy[ii][0];
        #pragma unroll
        for (int p = 0; p < 8; p++) {
            ull dx = dxp[p], dy = dyp[p], sx = sxp[p], sy = syp[p];
            udr[p] = fma2(dx, arr, udr[p]); udr[p] = fma2(dy, nai, udr[p]);
            udr[p] = fma2(sx, brr, udr[p]); udr[p] = fma2(sy, nbi, udr[p]);
            udi[p] = fma2(dx, aii, udi[p]); udi[p] = fma2(dy, arr, udi[p]);
            udi[p] = fma2(sx, bii, udi[p]); udi[p] = fma2(sy, brr, udi[p]);
            usr[p] = fma2(dx, crr, usr[p]); usr[p] = fma2(dy, nci, usr[p]);
            usi[p] = fma2(dx, cii, usi[p]); usi[p] = fma2(dy, crr, usi[p]);
        }
    }

    size_t base = (size_t)(modeoff + mode) * SEQ + o;
    #pragma unroll
    for (int p = 0; p < 8; p++) {
        g_pud[base + (2 * p) * 128]     = make_float2(lo32(udr[p]), lo32(udi[p]));
        g_pud[base + (2 * p + 1) * 128] = make_float2(hi32(udr[p]), hi32(udi[p]));
        g_pus[base + (2 * p) * 128]     = make_float2(lo32(usr[p]), lo32(usi[p]));
        g_pus[base + (2 * p + 1) * 128] = make_float2(hi32(usr[p]), hi32(usi[p]));
    }
}

// ---------------- batched T0 + reconstruction chain, levels 12..7 ------------------
__global__ void __launch_bounds__(32) k_rec_tail(const float* __restrict__ t0w,
                                                 const float* __restrict__ t0b,
                                                 const float* __restrict__ rce,
                                                 const float* __restrict__ rco,
                                                 float* __restrict__ xout) {
    __shared__ float sx[4][64];
    int bc = blockIdx.x;
    int tid = threadIdx.x;
    if (tid == 0) {
        float v[4];
        #pragma unroll
        for (int k = 0; k < 4; k++) v[k] = g_xfin[bc * 4 + k];
        #pragma unroll
        for (int kp = 0; kp < 4; kp++) {
            float a = __ldg(&t0b[kp]);
            #pragma unroll
            for (int k = 0; k < 4; k++) a += v[k] * __ldg(&t0w[kp * 4 + k]);
            sx[kp][0] = a;
        }
    }
    __syncthreads();
    int m = 1;
    for (int lev = 12; lev >= 7; lev--) {
        float ev[4], ov[4];
        if (tid < m) {
            float xs[4], ud[4];
            size_t off = (size_t)c_zoff[lev] * SEQ;
            #pragma unroll
            for (int k = 0; k < 4; k++) {
                size_t o = off + (size_t)(bc * 4 + k) * m + tid;
                xs[k] = sx[k][tid] + g_Us[o];
                ud[k] = g_Ud[o];
            }
            #pragma unroll
            for (int kp = 0; kp < 4; kp++) {
                float e = 0.f, o = 0.f;
                #pragma unroll
                for (int j = 0; j < 4; j++) {
                    e += xs[j] * __ldg(&rce[j * 4 + kp]) + ud[j] * __ldg(&rce[(4 + j) * 4 + kp]);
                    o += xs[j] * __ldg(&rco[j * 4 + kp]) + ud[j] * __ldg(&rco[(4 + j) * 4 + kp]);
                }
                ev[kp] = e; ov[kp] = o;
            }
        }
        __syncthreads();
        if (tid < m) {
            #pragma unroll
            for (int kp = 0; kp < 4; kp++) {
                sx[kp][2 * tid]     = ev[kp];
                sx[kp][2 * tid + 1] = ov[kp];
            }
        }
        __syncthreads();
        m <<= 1;
    }
    for (int i = tid; i < 256; i += 32)
        xout[(size_t)(bc * 4 + (i >> 6)) * 64 + (i & 63)] = sx[i >> 6][i & 63];
}

// ---------------- reconstruction levels 6..0 ----------------
__global__ void k_rec(const float* __restrict__ rin, int m, size_t off,
                      float* __restrict__ rout, int final_,
                      const float* __restrict__ rce, const float* __restrict__ rco) {
    int id = blockIdx.x * blockDim.x + threadIdx.x;
    if (id >= 512 * m) return;
    int t = id % m;
    int bc = id / m;
    int row0 = bc * 4;
    float xs[4], ud[4];
    #pragma unroll
    for (int k = 0; k < 4; k++) {
        size_t o = (size_t)(row0 + k) * m + t;
        xs[k] = rin[o] + g_Us[off + o];
        ud[k] = g_Ud[off + o];
    }
    float ev[4], ov[4];
    #pragma unroll
    for (int kp = 0; kp < 4; kp++) {
        float e = 0.f, o = 0.f;
        #pragma unroll
        for (int j = 0; j < 4; j++) {
            e += xs[j] * __ldg(&rce[j * 4 + kp]) + ud[j] * __ldg(&rce[(4 + j) * 4 + kp]);
            o += xs[j] * __ldg(&rco[j * 4 + kp]) + ud[j] * __ldg(&rco[(4 + j) * 4 + kp]);
        }
        ev[kp] = e; ov[kp] = o;
    }
    if (final_) {
        int b = bc >> 5, c = bc & 31;
        float* p0 = rout + (((size_t)b * NSEQ + 2 * t) * 32 + c) * 4;
        *((float4*)p0)         = make_float4(ev[0], ev[1], ev[2], ev[3]);
        *((float4*)(p0 + 128)) = make_float4(ov[0], ov[1], ov[2], ov[3]);
    } else {
        #pragma unroll
        for (int kp = 0; kp < 4; kp++) {
            size_t o = (size_t)(row0 + kp) * (2 * m);
            *((float2*)(rout + o) + t) = make_float2(ev[kp], ov[kp]);
        }
    }
}

// ---------------- host orchestration ----------------
extern "C" void kernel_launch(void* const* d_in, const int* in_sizes, int n_in,
                              void* d_out, int out_size) {
    const float* x   = (const float*)d_in[0];
    const float* wAr = (const float*)d_in[1];
    const float* wAi = (const float*)d_in[2];
    const float* wBr = (const float*)d_in[3];
    const float* wBi = (const float*)d_in[4];
    const float* wCr = (const float*)d_in[5];
    const float* wCi = (const float*)d_in[6];
    const float* ecs = (const float*)d_in[7];
    const float* ecd = (const float*)d_in[8];
    const float* rce = (const float*)d_in[9];
    const float* rco = (const float*)d_in[10];
    const float* t0w = (const float*)d_in[11];
    const float* t0b = (const float*)d_in[12];
    float* out = (float*)d_out;

    float *p_xt, *p_x0; float2 *p_z;
    cudaGetSymbolAddress((void**)&p_xt, g_xt);
    cudaGetSymbolAddress((void**)&p_x0, g_x0);
    cudaGetSymbolAddress((void**)&p_z,  g_z);

    cudaFuncSetAttribute(k_pfwd_all, cudaFuncAttributeMaxDynamicSharedMemorySize, 70000);

    k_tw<<<8, 256>>>();
    k_wt<<<dim3(16, 128, 6), dim3(32, 8)>>>(wAr, wAi, wBr, wBi, wCr, wCi);

    // ---- phase 1: decomposition (2 launches, parallel within each) ----
    k_dec05<<<16 * 256, 256>>>(x, ecs, ecd, p_x0);
    k_dec_rest<<<512, 128>>>(p_x0, ecs, ecd);

    // ---- phase 2: all forward FFTs in one launch ----
    k_pfwd_all<<<9728, 256, 66560>>>();

    // ---- phase 3: one mixing launch over all levels ----
    k_mix_all<<<775, 128>>>();

    // ---- phase 4: all inverse FFTs in one launch ----
    k_pinv_all<<<9728, 256, 35840>>>();

    // ---- phase 5: T0 + rec levels 12..7, then rec 6..0 ----
    k_rec_tail<<<512, 32>>>(t0w, t0b, rce, rco, p_xt);

    float* bufA = p_xt;
    float* bufB = (float*)p_z;
    float* cur = bufA;
    for (int lev = 6; lev >= 0; lev--) {
        int m = (NSEQ >> lev) >> 1;
        size_t off = (size_t)h_zoff[lev] * SEQ;
        int fin = (lev == 0);
        float* rout = fin ? out : ((cur == bufA) ? bufB : bufA);
        int tot = 512 * m;
        k_rec<<<(tot + 255) / 256, 256>>>(cur, m, off, rout, fin, rce, rco);
        if (!fin) cur = rout;
    }
    (void)in_sizes; (void)n_in; (void)out_size;
}